// round 7
// baseline (speedup 1.0000x reference)
#include <cuda_runtime.h>
#include <cuda_fp16.h>
#include <math.h>
#include <stdint.h>
#include <stddef.h>

// Problem constants
#define NN   50000
#define EE   640000
#define ETOT (EE + NN)      // 690000 (self-loops appended)
#define IND  128
#define HIDC 64
#define NH1  8
#define F1   (NH1 * HIDC)   // 512
#define NG   64
#define ODIM 2
#define SCAN_NB ((NN + 255) / 256)   // 196

// ---------------- scratch (device globals; no allocation allowed) ----------
__device__ __half g_Xh  [(size_t)NN * IND];   // fp16 copy of x
__device__ __half g_W1T [F1 * IND];           // W1 transposed [N=512][K=128] fp16
__device__ __half g_W2T [HIDC * F1];          // W2 transposed [N=64][K=512] fp16
__device__ __half g_H1h [(size_t)NN * F1];    // fp16 layer1 features (messages)
__device__ __half g_H1E [(size_t)NN * F1];    // fp16 elu(agg1+b1) (input to GEMM2)
__device__ __half g_H2h [(size_t)NN * HIDC];
__device__ float  g_AS1 [NN * NH1];
__device__ float  g_AD1 [NN * NH1];
__device__ float  g_AS2 [NN];
__device__ float  g_AD2 [NN];
__device__ float  g_POOL[NG * HIDC];
__device__ float  g_CNT [NG];
// CSR scratch
__device__ int g_deg   [NN];
__device__ int g_rowptr[NN + 1];
__device__ int g_cursor[NN];
__device__ int g_csr_src[ETOT];
__device__ int g_part  [SCAN_NB];

// ---------------- helpers ---------------------------------------------------
__device__ __forceinline__ void mma_f16(float c[4], const unsigned a[4], const unsigned b[2]) {
    asm volatile(
        "mma.sync.aligned.m16n8k16.row.col.f32.f16.f16.f32 "
        "{%0,%1,%2,%3}, {%4,%5,%6,%7}, {%8,%9}, {%0,%1,%2,%3};"
        : "+f"(c[0]), "+f"(c[1]), "+f"(c[2]), "+f"(c[3])
        : "r"(a[0]), "r"(a[1]), "r"(a[2]), "r"(a[3]), "r"(b[0]), "r"(b[1]));
}

__device__ __forceinline__ void cp_async16h(__half* dst, const __half* src, bool pred) {
    uint32_t s = (uint32_t)__cvta_generic_to_shared(dst);
    int sz = pred ? 16 : 0;
    asm volatile("cp.async.cg.shared.global [%0], [%1], 16, %2;\n"
                 :: "r"(s), "l"(src), "r"(sz));
}
__device__ __forceinline__ void cp_commit() {
    asm volatile("cp.async.commit_group;\n" ::: "memory");
}
template<int N>
__device__ __forceinline__ void cp_wait() {
    asm volatile("cp.async.wait_group %0;\n" :: "n"(N) : "memory");
}

// ---------------- prep: fp16 conversions + weight transposes ----------------
__global__ void prep_kernel(const float* __restrict__ x,
                            const float* __restrict__ W1,
                            const float* __restrict__ W2,
                            __half* __restrict__ xh,
                            __half* __restrict__ w1t,
                            __half* __restrict__ w2t) {
    size_t i = (size_t)blockIdx.x * blockDim.x + threadIdx.x;
    if (i < (size_t)NN * IND) xh[i] = __float2half_rn(x[i]);
    if (i < (size_t)F1 * IND) {
        int n = (int)(i / IND), k = (int)(i % IND);
        w1t[i] = __float2half_rn(W1[(size_t)k * F1 + n]);
    }
    if (i < (size_t)HIDC * F1) {
        int n = (int)(i / F1), k = (int)(i % F1);
        w2t[i] = __float2half_rn(W2[(size_t)k * HIDC + n]);
    }
}

__global__ void init_kernel(int* __restrict__ deg, float* __restrict__ pool) {
    int i = blockIdx.x * blockDim.x + threadIdx.x;
    if (i < NN)        deg[i] = 0;
    if (i < NG * HIDC) pool[i] = 0.f;
}

// ---------------- CSR construction ------------------------------------------
__global__ void deg_count_kernel(const int* __restrict__ ei, int* __restrict__ deg) {
    int e = blockIdx.x * blockDim.x + threadIdx.x;
    if (e >= ETOT) return;
    int d = (e < EE) ? ei[EE + e] : (e - EE);
    atomicAdd(&deg[d], 1);
}

// multi-block scan: phase A — per-block sums
__global__ void scan_a_kernel(const int* __restrict__ deg, int* __restrict__ part) {
    __shared__ int red[256];
    int i = blockIdx.x * 256 + threadIdx.x;
    int v = (i < NN) ? deg[i] : 0;
    red[threadIdx.x] = v;
    __syncthreads();
#pragma unroll
    for (int off = 128; off; off >>= 1) {
        if (threadIdx.x < off) red[threadIdx.x] += red[threadIdx.x + off];
        __syncthreads();
    }
    if (threadIdx.x == 0) part[blockIdx.x] = red[0];
}

// phase B — exclusive scan of block partials (1 block)
__global__ void scan_b_kernel(int* __restrict__ part) {
    __shared__ int sh[256];
    int t = threadIdx.x;
    int v = (t < SCAN_NB) ? part[t] : 0;
    sh[t] = v;
    __syncthreads();
#pragma unroll
    for (int off = 1; off < 256; off <<= 1) {
        int u = (t >= off) ? sh[t - off] : 0;
        __syncthreads();
        sh[t] += u;
        __syncthreads();
    }
    if (t < SCAN_NB) part[t] = sh[t] - v;   // exclusive
}

// phase C — block-local scan + global offset
__global__ void scan_c_kernel(const int* __restrict__ deg, const int* __restrict__ part,
                              int* __restrict__ rowptr, int* __restrict__ cursor) {
    __shared__ int sh[256];
    int t = threadIdx.x;
    int i = blockIdx.x * 256 + t;
    int v = (i < NN) ? deg[i] : 0;
    sh[t] = v;
    __syncthreads();
#pragma unroll
    for (int off = 1; off < 256; off <<= 1) {
        int u = (t >= off) ? sh[t - off] : 0;
        __syncthreads();
        sh[t] += u;
        __syncthreads();
    }
    if (i < NN) {
        int excl = part[blockIdx.x] + sh[t] - v;
        rowptr[i] = excl;
        cursor[i] = excl;
    }
    if (i == NN - 1) rowptr[NN] = ETOT;
}

__global__ void csr_fill_kernel(const int* __restrict__ ei, int* __restrict__ cursor,
                                int* __restrict__ csr_src) {
    int e = blockIdx.x * blockDim.x + threadIdx.x;
    if (e >= ETOT) return;
    int s, d;
    if (e < EE) { s = ei[e]; d = ei[EE + e]; } else { s = d = e - EE; }
    int pos = atomicAdd(&cursor[d], 1);
    csr_src[pos] = s;
}

// ---------------- fp16 tensor-core GEMM, cp.async double-buffered -----------
template<int BM, int BN, int WM, int NH, int MINB>
__global__ void __launch_bounds__((BM / WM) * (BN / 64) * 32, MINB)
mma_gemm_fused_kernel(const __half* __restrict__ A,
                      const __half* __restrict__ Bt,
                      __half* __restrict__ Ch,
                      const float* __restrict__ att_s,
                      const float* __restrict__ att_d,
                      float* __restrict__ AS,
                      float* __restrict__ AD,
                      int M, int N, int K) {
    constexpr int BK = 64;
    constexpr int WN = 64;
    constexpr int WARPS_M = BM / WM;
    constexpr int WARPS_N = BN / WN;
    constexpr int THREADS = WARPS_M * WARPS_N * 32;
    constexpr int MI = WM / 16;
    constexpr int NI = WN / 8;
    constexpr int LDA = BK + 8;
    constexpr int LDB = BK + 8;
    constexpr int A_IT = (BM * (BK / 8)) / THREADS;
    constexpr int B_IT = (BN * (BK / 8)) / THREADS;

    extern __shared__ char smem_raw[];
    __half* Asm = (__half*)smem_raw;
    __half* Bsm = (__half*)(smem_raw + 2 * BM * LDA * sizeof(__half));

    int tid  = threadIdx.x;
    int wid  = tid >> 5;
    int lane = tid & 31;
    int wm = wid % WARPS_M;
    int wn = wid / WARPS_M;
    int gid = lane >> 2;
    int tg  = lane & 3;

    int blockRow = blockIdx.y * BM;
    int blockCol = blockIdx.x * BN;

    float acc[MI][NI][4];
#pragma unroll
    for (int i = 0; i < MI; i++)
#pragma unroll
        for (int j = 0; j < NI; j++)
#pragma unroll
            for (int v = 0; v < 4; v++) acc[i][j][v] = 0.f;

    const int KT = K / BK;

    auto load_tiles = [&](int kt, int stage) {
        int k0 = kt * BK;
        __half* Ad = Asm + (size_t)stage * BM * LDA;
        __half* Bd = Bsm + (size_t)stage * BN * LDB;
#pragma unroll
        for (int v = 0; v < A_IT; v++) {
            int idx = tid + v * THREADS;
            int r = idx >> 3, c = idx & 7;
            int gr = blockRow + r;
            cp_async16h(Ad + r * LDA + c * 8,
                        A + (size_t)gr * K + k0 + c * 8, gr < M);
        }
#pragma unroll
        for (int v = 0; v < B_IT; v++) {
            int idx = tid + v * THREADS;
            int r = idx >> 3, c = idx & 7;
            cp_async16h(Bd + r * LDB + c * 8,
                        Bt + (size_t)(blockCol + r) * K + k0 + c * 8, true);
        }
    };

    load_tiles(0, 0);
    cp_commit();

    int buf = 0;
    for (int kt = 0; kt < KT; kt++) {
        if (kt + 1 < KT) {
            load_tiles(kt + 1, buf ^ 1);
            cp_commit();
            cp_wait<1>();
        } else {
            cp_wait<0>();
        }
        __syncthreads();

        const __half* Asb = Asm + (size_t)buf * BM * LDA;
        const __half* Bsb = Bsm + (size_t)buf * BN * LDB;
#pragma unroll
        for (int kk = 0; kk < BK; kk += 16) {
            unsigned a[MI][4], b[NI][2];
#pragma unroll
            for (int mi = 0; mi < MI; mi++) {
                const __half* ap = Asb + (size_t)(wm * WM + mi * 16 + gid) * LDA + kk + 2 * tg;
                a[mi][0] = *(const unsigned*)(ap);
                a[mi][1] = *(const unsigned*)(ap + 8 * LDA);
                a[mi][2] = *(const unsigned*)(ap + 8);
                a[mi][3] = *(const unsigned*)(ap + 8 * LDA + 8);
            }
#pragma unroll
            for (int ni = 0; ni < NI; ni++) {
                const __half* bp = Bsb + (size_t)(wn * WN + ni * 8 + gid) * LDB + kk + 2 * tg;
                b[ni][0] = *(const unsigned*)(bp);
                b[ni][1] = *(const unsigned*)(bp + 8);
            }
#pragma unroll
            for (int mi = 0; mi < MI; mi++)
#pragma unroll
                for (int ni = 0; ni < NI; ni++)
                    mma_f16(acc[mi][ni], a[mi], b[ni]);
        }
        __syncthreads();
        buf ^= 1;
    }

    // ---- epilogue: fp16 write + fused per-head attention dots ----
    int head = (blockCol >> 6) + wn;
    float asv[NI][2], adv[NI][2];
#pragma unroll
    for (int ni = 0; ni < NI; ni++) {
        int c = head * 64 + ni * 8 + tg * 2;
        asv[ni][0] = att_s[c];     asv[ni][1] = att_s[c + 1];
        adv[ni][0] = att_d[c];     adv[ni][1] = att_d[c + 1];
    }

#pragma unroll
    for (int mi = 0; mi < MI; mi++) {
#pragma unroll
        for (int rh = 0; rh < 2; rh++) {
            int row = blockRow + wm * WM + mi * 16 + gid + rh * 8;
            float ps = 0.f, pd = 0.f;
#pragma unroll
            for (int ni = 0; ni < NI; ni++) {
                float c0 = acc[mi][ni][rh * 2];
                float c1 = acc[mi][ni][rh * 2 + 1];
                ps = fmaf(c0, asv[ni][0], fmaf(c1, asv[ni][1], ps));
                pd = fmaf(c0, adv[ni][0], fmaf(c1, adv[ni][1], pd));
            }
            ps += __shfl_xor_sync(0xffffffffu, ps, 1);
            ps += __shfl_xor_sync(0xffffffffu, ps, 2);
            pd += __shfl_xor_sync(0xffffffffu, pd, 1);
            pd += __shfl_xor_sync(0xffffffffu, pd, 2);
            if (tg == 0 && row < M) {
                AS[row * NH + head] = ps;
                AD[row * NH + head] = pd;
            }
            if (row < M) {
                int col = blockCol + wn * WN;
#pragma unroll
                for (int ni = 0; ni < NI; ni++) {
                    *(__half2*)(Ch + (size_t)row * N + col + ni * 8 + tg * 2) =
                        __floats2half2_rn(acc[mi][ni][rh * 2], acc[mi][ni][rh * 2 + 1]);
                }
            }
        }
    }
}

// ---------------- layer1 fused softmax+gather --------------------------------
// One block (256 thr) per dst row. 4 edge-groups of 64 threads; each thread
// loads 16B (8 fp16 channels) per edge. Cross-group reduce via smem.
__global__ void gather1_kernel(const int* __restrict__ rowptr,
                               const int* __restrict__ csr_src,
                               const float* __restrict__ AS,
                               const float* __restrict__ AD,
                               const __half* __restrict__ h1h,
                               const float* __restrict__ b1,
                               __half* __restrict__ out) {
    __shared__ int   ssrc[32];
    __shared__ float sex[32][NH1];
    __shared__ float sacc[4][F1];     // 8KB partials
    __shared__ float sden[4][NH1];

    int row = blockIdx.x;
    int tid = threadIdx.x;
    int g = tid >> 6;                 // edge group 0..3
    int i = tid & 63;                 // 16B chunk slot; channels i*8..i*8+7
    int head = i >> 3;
    int start = rowptr[row], end = rowptr[row + 1];

    float acc0 = 0.f, acc1 = 0.f, acc2 = 0.f, acc3 = 0.f;
    float acc4 = 0.f, acc5 = 0.f, acc6 = 0.f, acc7 = 0.f;
    float den = 0.f;

    for (int j0 = start; j0 < end; j0 += 32) {
        int m = end - j0; if (m > 32) m = 32;
        if (tid < m * NH1) {
            int e = tid >> 3, hh = tid & 7;
            int s = csr_src[j0 + e];
            if (hh == 0) ssrc[e] = s;
            float lg = AS[s * NH1 + hh] + AD[row * NH1 + hh];
            lg = (lg > 0.f) ? lg : 0.2f * lg;
            sex[e][hh] = __expf(lg);
        }
        __syncthreads();
        for (int e = g; e < m; e += 4) {
            int s = ssrc[e];
            float a = sex[e][head];
            uint4 u = *(const uint4*)(h1h + (size_t)s * F1 + i * 8);
            float2 f0 = __half22float2(*(__half2*)&u.x);
            float2 f1 = __half22float2(*(__half2*)&u.y);
            float2 f2 = __half22float2(*(__half2*)&u.z);
            float2 f3 = __half22float2(*(__half2*)&u.w);
            acc0 = fmaf(f0.x, a, acc0); acc1 = fmaf(f0.y, a, acc1);
            acc2 = fmaf(f1.x, a, acc2); acc3 = fmaf(f1.y, a, acc3);
            acc4 = fmaf(f2.x, a, acc4); acc5 = fmaf(f2.y, a, acc5);
            acc6 = fmaf(f3.x, a, acc6); acc7 = fmaf(f3.y, a, acc7);
            den += a;
        }
        __syncthreads();
    }

    // write partials (vectorized, conflict-bounded)
    float4* prow = (float4*)&sacc[g][i * 8];
    prow[0] = make_float4(acc0, acc1, acc2, acc3);
    prow[1] = make_float4(acc4, acc5, acc6, acc7);
    if ((i & 7) == 0) sden[g][head] = den;   // identical across the 8 threads of (g,head)
    __syncthreads();

    // reduce: thread t handles channels 2t, 2t+1
    int ch = tid * 2;
    float vx = sacc[0][ch] + sacc[1][ch] + sacc[2][ch] + sacc[3][ch];
    float vy = sacc[0][ch + 1] + sacc[1][ch + 1] + sacc[2][ch + 1] + sacc[3][ch + 1];
    int hh = tid >> 5;
    float dtot = sden[0][hh] + sden[1][hh] + sden[2][hh] + sden[3][hh];
    float invd = 1.f / (dtot + 1e-16f);
    vx = vx * invd + b1[ch];
    vy = vy * invd + b1[ch + 1];
    vx = (vx > 0.f) ? vx : (__expf(vx) - 1.f);
    vy = (vy > 0.f) ? vy : (__expf(vy) - 1.f);
    *(__half2*)(out + (size_t)row * F1 + ch) = __floats2half2_rn(vx, vy);
}

// ---------------- layer2 fused softmax+gather --------------------------------
// One warp per dst; 4 edge-subgroups of 8 lanes; lane loads 16B (8 channels).
__global__ void gather2_kernel(const int* __restrict__ rowptr,
                               const int* __restrict__ csr_src,
                               const float* __restrict__ AS,
                               const float* __restrict__ AD,
                               const __half* __restrict__ h2h,
                               const float* __restrict__ b2,
                               const int* __restrict__ batch,
                               float* __restrict__ pool) {
    int w = (blockIdx.x * blockDim.x + threadIdx.x) >> 5;
    int lane = threadIdx.x & 31;
    if (w >= NN) return;
    int sub = lane >> 3;      // edge subgroup 0..3
    int i = lane & 7;         // channels i*8..i*8+7
    int start = rowptr[w], end = rowptr[w + 1];
    float ad_r = AD[w];

    float acc0 = 0.f, acc1 = 0.f, acc2 = 0.f, acc3 = 0.f;
    float acc4 = 0.f, acc5 = 0.f, acc6 = 0.f, acc7 = 0.f;
    float den = 0.f;

    for (int j = start + sub; j < end; j += 4) {
        int s = csr_src[j];
        float lg = AS[s] + ad_r;
        lg = (lg > 0.f) ? lg : 0.2f * lg;
        float a = __expf(lg);
        uint4 u = *(const uint4*)(h2h + (size_t)s * HIDC + i * 8);
        float2 f0 = __half22float2(*(__half2*)&u.x);
        float2 f1 = __half22float2(*(__half2*)&u.y);
        float2 f2 = __half22float2(*(__half2*)&u.z);
        float2 f3 = __half22float2(*(__half2*)&u.w);
        acc0 = fmaf(f0.x, a, acc0); acc1 = fmaf(f0.y, a, acc1);
        acc2 = fmaf(f1.x, a, acc2); acc3 = fmaf(f1.y, a, acc3);
        acc4 = fmaf(f2.x, a, acc4); acc5 = fmaf(f2.y, a, acc5);
        acc6 = fmaf(f3.x, a, acc6); acc7 = fmaf(f3.y, a, acc7);
        den += a;
    }
    __syncwarp();
    // reduce across the 4 subgroups (lanes i, i+8, i+16, i+24)
#pragma unroll
    for (int o = 8; o <= 16; o <<= 1) {
        acc0 += __shfl_xor_sync(0xffffffffu, acc0, o);
        acc1 += __shfl_xor_sync(0xffffffffu, acc1, o);
        acc2 += __shfl_xor_sync(0xffffffffu, acc2, o);
        acc3 += __shfl_xor_sync(0xffffffffu, acc3, o);
        acc4 += __shfl_xor_sync(0xffffffffu, acc4, o);
        acc5 += __shfl_xor_sync(0xffffffffu, acc5, o);
        acc6 += __shfl_xor_sync(0xffffffffu, acc6, o);
        acc7 += __shfl_xor_sync(0xffffffffu, acc7, o);
        den  += __shfl_xor_sync(0xffffffffu, den,  o);
    }
    if (sub == 0) {
        float invd = 1.f / (den + 1e-16f);
        int g = batch[w];
        float accs[8] = {acc0, acc1, acc2, acc3, acc4, acc5, acc6, acc7};
#pragma unroll
        for (int c = 0; c < 8; c++) {
            int ch = i * 8 + c;
            float v = accs[c] * invd + b2[ch];
            v = (v > 0.f) ? v : (__expf(v) - 1.f);
            atomicAdd(&pool[g * HIDC + ch], v);
        }
    }
}

// ---------------- graph node counts: binary search on sorted batch ----------
__global__ void cnt_kernel(const int* __restrict__ batch, float* __restrict__ cnt) {
    int g = threadIdx.x;
    if (g >= NG) return;
    int lo = 0, hi = NN;
    while (lo < hi) { int mid = (lo + hi) >> 1; if (batch[mid] < g) lo = mid + 1; else hi = mid; }
    int a = lo, b = NN;
    while (a < b) { int mid = (a + b) >> 1; if (batch[mid] < g + 1) a = mid + 1; else b = mid; }
    cnt[g] = (float)(a - lo);
}

// ---------------- final FC ----------------------------------------------------
__global__ void final_fc_kernel(const float* __restrict__ pool,
                                const float* __restrict__ cnt,
                                const float* __restrict__ fcw,
                                const float* __restrict__ fcb,
                                float* __restrict__ out) {
    int t = threadIdx.x;
    if (t >= NG * ODIM) return;
    int g = t >> 1, o = t & 1;
    float s = 0.f;
#pragma unroll
    for (int c = 0; c < HIDC; c++) s += pool[g * HIDC + c] * fcw[c * ODIM + o];
    float cc = cnt[g];
    cc = (cc > 1.f) ? cc : 1.f;
    out[g * ODIM + o] = s / cc + fcb[o];
}

// ---------------- launcher ----------------------------------------------------
static inline int nblk(size_t n, int t) { return (int)((n + t - 1) / t); }

extern "C" void kernel_launch(void* const* d_in, const int* in_sizes, int n_in,
                              void* d_out, int out_size) {
    const float* x      = (const float*)d_in[0];
    const float* W1     = (const float*)d_in[1];
    const float* att_s1 = (const float*)d_in[2];
    const float* att_d1 = (const float*)d_in[3];
    const float* b1     = (const float*)d_in[4];
    const float* W2     = (const float*)d_in[5];
    const float* att_s2 = (const float*)d_in[6];
    const float* att_d2 = (const float*)d_in[7];
    const float* b2     = (const float*)d_in[8];
    const float* fcw    = (const float*)d_in[9];
    const float* fcb    = (const float*)d_in[10];
    const int*   ei     = (const int*)d_in[11];
    const int*   batch  = (const int*)d_in[12];
    float* out = (float*)d_out;

    float *AS1, *AD1, *AS2, *AD2, *POOL, *CNT;
    __half *Xh, *W1T, *W2T, *H1h, *H1E, *H2h;
    int *DEG, *ROWPTR, *CURSOR, *CSRC, *PART;
    cudaGetSymbolAddress((void**)&Xh,    g_Xh);
    cudaGetSymbolAddress((void**)&W1T,   g_W1T);
    cudaGetSymbolAddress((void**)&W2T,   g_W2T);
    cudaGetSymbolAddress((void**)&H1h,   g_H1h);
    cudaGetSymbolAddress((void**)&H1E,   g_H1E);
    cudaGetSymbolAddress((void**)&H2h,   g_H2h);
    cudaGetSymbolAddress((void**)&AS1,   g_AS1);
    cudaGetSymbolAddress((void**)&AD1,   g_AD1);
    cudaGetSymbolAddress((void**)&AS2,   g_AS2);
    cudaGetSymbolAddress((void**)&AD2,   g_AD2);
    cudaGetSymbolAddress((void**)&POOL,  g_POOL);
    cudaGetSymbolAddress((void**)&CNT,   g_CNT);
    cudaGetSymbolAddress((void**)&DEG,    g_deg);
    cudaGetSymbolAddress((void**)&ROWPTR, g_rowptr);
    cudaGetSymbolAddress((void**)&CURSOR, g_cursor);
    cudaGetSymbolAddress((void**)&CSRC,   g_csr_src);
    cudaGetSymbolAddress((void**)&PART,   g_part);

    constexpr int SM1 = 2 * (128 * 72 + 128 * 72) * 2;  // 73728
    constexpr int SM2 = 2 * (64 * 72 + 64 * 72) * 2;    // 36864
    cudaFuncSetAttribute((const void*)mma_gemm_fused_kernel<128, 128, 32, NH1, 2>,
                         cudaFuncAttributeMaxDynamicSharedMemorySize, SM1);
    cudaFuncSetAttribute((const void*)mma_gemm_fused_kernel<64, 64, 16, 1, 6>,
                         cudaFuncAttributeMaxDynamicSharedMemorySize, SM2);

    // 1: init   2: prep   3: deg   4: GEMM1 (profiled slot)
    init_kernel<<<nblk(NN, 256), 256>>>(DEG, POOL);
    prep_kernel<<<nblk((size_t)NN * IND, 256), 256>>>(x, W1, W2, Xh, W1T, W2T);
    deg_count_kernel<<<nblk(ETOT, 256), 256>>>(ei, DEG);
    {
        dim3 grid(F1 / 128, (NN + 127) / 128);
        mma_gemm_fused_kernel<128, 128, 32, NH1, 2><<<grid, 256, SM1>>>(
            Xh, W1T, H1h, att_s1, att_d1, AS1, AD1, NN, F1, IND);
    }
    // 5-7: 3-phase scan   8: csr_fill   9: cnt
    scan_a_kernel<<<SCAN_NB, 256>>>(DEG, PART);
    scan_b_kernel<<<1, 256>>>(PART);
    scan_c_kernel<<<SCAN_NB, 256>>>(DEG, PART, ROWPTR, CURSOR);
    csr_fill_kernel<<<nblk(ETOT, 256), 256>>>(ei, CURSOR, CSRC);
    cnt_kernel<<<1, 64>>>(batch, CNT);

    // 10: layer1 gather (fused softmax + bias + elu, fp16 out)
    gather1_kernel<<<NN, 256>>>(ROWPTR, CSRC, AS1, AD1, H1h, b1, H1E);

    // 11: GEMM2 (fused dots, all fp16)
    {
        dim3 grid(1, (NN + 63) / 64);
        mma_gemm_fused_kernel<64, 64, 16, 1, 6><<<grid, 128, SM2>>>(
            H1E, W2T, H2h, att_s2, att_d2, AS2, AD2, NN, HIDC, F1);
    }

    // 12: layer2 gather (fused softmax + elu + pool)
    gather2_kernel<<<nblk((size_t)NN * 32, 256), 256>>>(
        ROWPTR, CSRC, AS2, AD2, H2h, b2, batch, POOL);

    // 13: final FC
    final_fc_kernel<<<1, 128>>>(POOL, CNT, fcw, fcb, out);
}

// round 8
// speedup vs baseline: 1.5206x; 1.5206x over previous
#include <cuda_runtime.h>
#include <cuda_fp16.h>
#include <math.h>
#include <stdint.h>
#include <stddef.h>

// Problem constants
#define NN   50000
#define EE   640000
#define ETOT (EE + NN)      // 690000 (self-loops appended)
#define IND  128
#define HIDC 64
#define NH1  8
#define F1   (NH1 * HIDC)   // 512
#define NG   64
#define ODIM 2
#define SCAN_NB ((NN + 255) / 256)   // 196

// ---------------- scratch (device globals; no allocation allowed) ----------
__device__ __half g_Xh  [(size_t)NN * IND];   // fp16 copy of x
__device__ __half g_W1T [F1 * IND];           // W1 transposed [N=512][K=128] fp16
__device__ __half g_W2T [HIDC * F1];          // W2 transposed [N=64][K=512] fp16
__device__ __half g_H1h [(size_t)NN * F1];    // fp16 layer1 features (messages)
__device__ __half g_H1E [(size_t)NN * F1];    // fp16 elu(agg1+b1) (input to GEMM2)
__device__ __half g_H2h [(size_t)NN * HIDC];
__device__ float  g_AS1 [NN * NH1];
__device__ float  g_AD1 [NN * NH1];
__device__ float  g_AS2 [NN];
__device__ float  g_AD2 [NN];
__device__ float  g_POOL[NG * HIDC];
__device__ float  g_CNT [NG];
// CSR scratch
__device__ int g_deg   [NN];
__device__ int g_rowptr[NN + 1];
__device__ int g_cursor[NN];
__device__ int g_csr_src[ETOT];
__device__ int g_part  [SCAN_NB];

// ---------------- helpers ---------------------------------------------------
__device__ __forceinline__ void mma_f16(float c[4], const unsigned a[4], const unsigned b[2]) {
    asm volatile(
        "mma.sync.aligned.m16n8k16.row.col.f32.f16.f16.f32 "
        "{%0,%1,%2,%3}, {%4,%5,%6,%7}, {%8,%9}, {%0,%1,%2,%3};"
        : "+f"(c[0]), "+f"(c[1]), "+f"(c[2]), "+f"(c[3])
        : "r"(a[0]), "r"(a[1]), "r"(a[2]), "r"(a[3]), "r"(b[0]), "r"(b[1]));
}

__device__ __forceinline__ void ldsm_x4(unsigned& r0, unsigned& r1, unsigned& r2, unsigned& r3,
                                        uint32_t addr) {
    asm volatile("ldmatrix.sync.aligned.m8n8.x4.shared.b16 {%0,%1,%2,%3}, [%4];"
                 : "=r"(r0), "=r"(r1), "=r"(r2), "=r"(r3) : "r"(addr));
}

__device__ __forceinline__ uint32_t smem_u32(const void* p) {
    return (uint32_t)__cvta_generic_to_shared(p);
}

__device__ __forceinline__ void cp_async16h(__half* dst, const __half* src, bool pred) {
    uint32_t s = (uint32_t)__cvta_generic_to_shared(dst);
    int sz = pred ? 16 : 0;
    asm volatile("cp.async.cg.shared.global [%0], [%1], 16, %2;\n"
                 :: "r"(s), "l"(src), "r"(sz));
}
__device__ __forceinline__ void cp_commit() {
    asm volatile("cp.async.commit_group;\n" ::: "memory");
}
template<int N>
__device__ __forceinline__ void cp_wait() {
    asm volatile("cp.async.wait_group %0;\n" :: "n"(N) : "memory");
}

// ---------------- prep: fp16 conversions + weight transposes ----------------
__global__ void prep_kernel(const float* __restrict__ x,
                            const float* __restrict__ W1,
                            const float* __restrict__ W2,
                            __half* __restrict__ xh,
                            __half* __restrict__ w1t,
                            __half* __restrict__ w2t) {
    size_t i = (size_t)blockIdx.x * blockDim.x + threadIdx.x;
    if (i < (size_t)NN * IND) xh[i] = __float2half_rn(x[i]);
    if (i < (size_t)F1 * IND) {
        int n = (int)(i / IND), k = (int)(i % IND);
        w1t[i] = __float2half_rn(W1[(size_t)k * F1 + n]);
    }
    if (i < (size_t)HIDC * F1) {
        int n = (int)(i / F1), k = (int)(i % F1);
        w2t[i] = __float2half_rn(W2[(size_t)k * HIDC + n]);
    }
}

__global__ void init_kernel(int* __restrict__ deg, float* __restrict__ pool) {
    int i = blockIdx.x * blockDim.x + threadIdx.x;
    if (i < NN)        deg[i] = 0;
    if (i < NG * HIDC) pool[i] = 0.f;
}

// ---------------- CSR construction ------------------------------------------
__global__ void deg_count_kernel(const int* __restrict__ ei, int* __restrict__ deg) {
    int e = blockIdx.x * blockDim.x + threadIdx.x;
    if (e >= ETOT) return;
    int d = (e < EE) ? ei[EE + e] : (e - EE);
    atomicAdd(&deg[d], 1);
}

__global__ void scan_a_kernel(const int* __restrict__ deg, int* __restrict__ part) {
    __shared__ int red[256];
    int i = blockIdx.x * 256 + threadIdx.x;
    int v = (i < NN) ? deg[i] : 0;
    red[threadIdx.x] = v;
    __syncthreads();
#pragma unroll
    for (int off = 128; off; off >>= 1) {
        if (threadIdx.x < off) red[threadIdx.x] += red[threadIdx.x + off];
        __syncthreads();
    }
    if (threadIdx.x == 0) part[blockIdx.x] = red[0];
}

__global__ void scan_b_kernel(int* __restrict__ part) {
    __shared__ int sh[256];
    int t = threadIdx.x;
    int v = (t < SCAN_NB) ? part[t] : 0;
    sh[t] = v;
    __syncthreads();
#pragma unroll
    for (int off = 1; off < 256; off <<= 1) {
        int u = (t >= off) ? sh[t - off] : 0;
        __syncthreads();
        sh[t] += u;
        __syncthreads();
    }
    if (t < SCAN_NB) part[t] = sh[t] - v;   // exclusive
}

__global__ void scan_c_kernel(const int* __restrict__ deg, const int* __restrict__ part,
                              int* __restrict__ rowptr, int* __restrict__ cursor) {
    __shared__ int sh[256];
    int t = threadIdx.x;
    int i = blockIdx.x * 256 + t;
    int v = (i < NN) ? deg[i] : 0;
    sh[t] = v;
    __syncthreads();
#pragma unroll
    for (int off = 1; off < 256; off <<= 1) {
        int u = (t >= off) ? sh[t - off] : 0;
        __syncthreads();
        sh[t] += u;
        __syncthreads();
    }
    if (i < NN) {
        int excl = part[blockIdx.x] + sh[t] - v;
        rowptr[i] = excl;
        cursor[i] = excl;
    }
    if (i == NN - 1) rowptr[NN] = ETOT;
}

__global__ void csr_fill_kernel(const int* __restrict__ ei, int* __restrict__ cursor,
                                int* __restrict__ csr_src) {
    int e = blockIdx.x * blockDim.x + threadIdx.x;
    if (e >= ETOT) return;
    int s, d;
    if (e < EE) { s = ei[e]; d = ei[EE + e]; } else { s = d = e - EE; }
    int pos = atomicAdd(&cursor[d], 1);
    csr_src[pos] = s;
}

// ---------------- fp16 tensor-core GEMM, cp.async + ldmatrix ----------------
template<int BM, int BN, int WM, int NH, int MINB>
__global__ void __launch_bounds__((BM / WM) * (BN / 64) * 32, MINB)
mma_gemm_fused_kernel(const __half* __restrict__ A,
                      const __half* __restrict__ Bt,
                      __half* __restrict__ Ch,
                      const float* __restrict__ att_s,
                      const float* __restrict__ att_d,
                      float* __restrict__ AS,
                      float* __restrict__ AD,
                      int M, int N, int K) {
    constexpr int BK = 64;
    constexpr int WN = 64;
    constexpr int WARPS_M = BM / WM;
    constexpr int WARPS_N = BN / WN;
    constexpr int THREADS = WARPS_M * WARPS_N * 32;
    constexpr int MI = WM / 16;
    constexpr int NI = WN / 8;
    constexpr int NJ = NI / 2;
    constexpr int LDA = BK + 8;   // 72 halves -> ldmatrix rows conflict-free
    constexpr int LDB = BK + 8;
    constexpr int A_IT = (BM * (BK / 8)) / THREADS;
    constexpr int B_IT = (BN * (BK / 8)) / THREADS;

    extern __shared__ char smem_raw[];
    __half* Asm = (__half*)smem_raw;
    __half* Bsm = (__half*)(smem_raw + 2 * BM * LDA * sizeof(__half));

    int tid  = threadIdx.x;
    int wid  = tid >> 5;
    int lane = tid & 31;
    int wm = wid % WARPS_M;
    int wn = wid / WARPS_M;
    int gid = lane >> 2;
    int tg  = lane & 3;

    int blockRow = blockIdx.y * BM;
    int blockCol = blockIdx.x * BN;

    float acc[MI][NI][4];
#pragma unroll
    for (int i = 0; i < MI; i++)
#pragma unroll
        for (int j = 0; j < NI; j++)
#pragma unroll
            for (int v = 0; v < 4; v++) acc[i][j][v] = 0.f;

    const int KT = K / BK;

    auto load_tiles = [&](int kt, int stage) {
        int k0 = kt * BK;
        __half* Ad = Asm + (size_t)stage * BM * LDA;
        __half* Bd = Bsm + (size_t)stage * BN * LDB;
#pragma unroll
        for (int v = 0; v < A_IT; v++) {
            int idx = tid + v * THREADS;
            int r = idx >> 3, c = idx & 7;
            int gr = blockRow + r;
            cp_async16h(Ad + r * LDA + c * 8,
                        A + (size_t)gr * K + k0 + c * 8, gr < M);
        }
#pragma unroll
        for (int v = 0; v < B_IT; v++) {
            int idx = tid + v * THREADS;
            int r = idx >> 3, c = idx & 7;
            cp_async16h(Bd + r * LDB + c * 8,
                        Bt + (size_t)(blockCol + r) * K + k0 + c * 8, true);
        }
    };

    load_tiles(0, 0);
    cp_commit();

    // per-lane ldmatrix row offsets (element units, stage-relative)
    // A x4 covers {(m0,kk),(m0+8,kk),(m0,kk+8),(m0+8,kk+8)}
    int a_row = wm * WM + (lane & 15);
    int a_col = (lane >> 4) * 8;
    // B x4 covers {(n0,kk),(n0,kk+8),(n0+8,kk),(n0+8,kk+8)} -> b[2j][0],b[2j][1],b[2j+1][0],b[2j+1][1]
    int b_row = wn * WN + (lane & 7) + (lane >> 4) * 8;
    int b_col = ((lane >> 3) & 1) * 8;

    int buf = 0;
    for (int kt = 0; kt < KT; kt++) {
        if (kt + 1 < KT) {
            load_tiles(kt + 1, buf ^ 1);
            cp_commit();
            cp_wait<1>();
        } else {
            cp_wait<0>();
        }
        __syncthreads();

        const __half* Asb = Asm + (size_t)buf * BM * LDA;
        const __half* Bsb = Bsm + (size_t)buf * BN * LDB;
        uint32_t a_addr[MI], b_addr[NJ];
#pragma unroll
        for (int mi = 0; mi < MI; mi++)
            a_addr[mi] = smem_u32(Asb + (size_t)(a_row + mi * 16) * LDA + a_col);
#pragma unroll
        for (int nj = 0; nj < NJ; nj++)
            b_addr[nj] = smem_u32(Bsb + (size_t)(b_row + nj * 16) * LDB + b_col);

#pragma unroll
        for (int kk = 0; kk < BK; kk += 16) {
            unsigned a[MI][4], b[NI][2];
#pragma unroll
            for (int mi = 0; mi < MI; mi++)
                ldsm_x4(a[mi][0], a[mi][1], a[mi][2], a[mi][3], a_addr[mi] + kk * 2);
#pragma unroll
            for (int nj = 0; nj < NJ; nj++)
                ldsm_x4(b[2 * nj][0], b[2 * nj][1], b[2 * nj + 1][0], b[2 * nj + 1][1],
                        b_addr[nj] + kk * 2);
#pragma unroll
            for (int mi = 0; mi < MI; mi++)
#pragma unroll
                for (int ni = 0; ni < NI; ni++)
                    mma_f16(acc[mi][ni], a[mi], b[ni]);
        }
        __syncthreads();
        buf ^= 1;
    }

    // ---- epilogue: fp16 write + fused per-head attention dots ----
    int head = (blockCol >> 6) + wn;
    float asv[NI][2], adv[NI][2];
#pragma unroll
    for (int ni = 0; ni < NI; ni++) {
        int c = head * 64 + ni * 8 + tg * 2;
        asv[ni][0] = att_s[c];     asv[ni][1] = att_s[c + 1];
        adv[ni][0] = att_d[c];     adv[ni][1] = att_d[c + 1];
    }

#pragma unroll
    for (int mi = 0; mi < MI; mi++) {
#pragma unroll
        for (int rh = 0; rh < 2; rh++) {
            int row = blockRow + wm * WM + mi * 16 + gid + rh * 8;
            float ps = 0.f, pd = 0.f;
#pragma unroll
            for (int ni = 0; ni < NI; ni++) {
                float c0 = acc[mi][ni][rh * 2];
                float c1 = acc[mi][ni][rh * 2 + 1];
                ps = fmaf(c0, asv[ni][0], fmaf(c1, asv[ni][1], ps));
                pd = fmaf(c0, adv[ni][0], fmaf(c1, adv[ni][1], pd));
            }
            ps += __shfl_xor_sync(0xffffffffu, ps, 1);
            ps += __shfl_xor_sync(0xffffffffu, ps, 2);
            pd += __shfl_xor_sync(0xffffffffu, pd, 1);
            pd += __shfl_xor_sync(0xffffffffu, pd, 2);
            if (tg == 0 && row < M) {
                AS[row * NH + head] = ps;
                AD[row * NH + head] = pd;
            }
            if (row < M) {
                int col = blockCol + wn * WN;
#pragma unroll
                for (int ni = 0; ni < NI; ni++) {
                    *(__half2*)(Ch + (size_t)row * N + col + ni * 8 + tg * 2) =
                        __floats2half2_rn(acc[mi][ni][rh * 2], acc[mi][ni][rh * 2 + 1]);
                }
            }
        }
    }
}

// ---------------- layer1 fused softmax+gather (Round-6 version) -------------
__global__ void gather1_kernel(const int* __restrict__ rowptr,
                               const int* __restrict__ csr_src,
                               const float* __restrict__ AS,
                               const float* __restrict__ AD,
                               const __half2* __restrict__ h1h,
                               const float* __restrict__ b1,
                               __half* __restrict__ out) {
    __shared__ int   ssrc[32];
    __shared__ float sex[32][NH1];

    int row = blockIdx.x;
    int tid = threadIdx.x;
    int ch = tid * 2;
    int h = tid >> 5;                  // head = ch/64
    int start = rowptr[row], end = rowptr[row + 1];

    float accx = 0.f, accy = 0.f, den = 0.f;

    for (int j0 = start; j0 < end; j0 += 32) {
        int m = end - j0; if (m > 32) m = 32;
        if (tid < m * NH1) {
            int e = tid >> 3, hh = tid & 7;
            int s = csr_src[j0 + e];
            if (hh == 0) ssrc[e] = s;
            float lg = AS[s * NH1 + hh] + AD[row * NH1 + hh];
            lg = (lg > 0.f) ? lg : 0.2f * lg;
            sex[e][hh] = __expf(lg);
        }
        __syncthreads();
#pragma unroll 4
        for (int e = 0; e < m; e++) {
            int s = ssrc[e];
            float a = sex[e][h];
            float2 v = __half22float2(h1h[(size_t)s * (F1 / 2) + tid]);
            accx = fmaf(v.x, a, accx);
            accy = fmaf(v.y, a, accy);
            den += a;
        }
        __syncthreads();
    }
    float invd = 1.f / (den + 1e-16f);
    float vx = accx * invd + b1[ch];
    float vy = accy * invd + b1[ch + 1];
    vx = (vx > 0.f) ? vx : (__expf(vx) - 1.f);
    vy = (vy > 0.f) ? vy : (__expf(vy) - 1.f);
    *(__half2*)(out + (size_t)row * F1 + ch) = __floats2half2_rn(vx, vy);
}

// ---------------- layer2 fused softmax+gather (Round-6 version) -------------
__global__ void gather2_kernel(const int* __restrict__ rowptr,
                               const int* __restrict__ csr_src,
                               const float* __restrict__ AS,
                               const float* __restrict__ AD,
                               const __half2* __restrict__ h2h,
                               const float* __restrict__ b2,
                               const int* __restrict__ batch,
                               float* __restrict__ pool) {
    int w = (blockIdx.x * blockDim.x + threadIdx.x) >> 5;
    int lane = threadIdx.x & 31;
    if (w >= NN) return;
    int start = rowptr[w], end = rowptr[w + 1];
    float ad_r = AD[w];
    int ch = lane * 2;
    float accx = 0.f, accy = 0.f, den = 0.f;

    for (int j0 = start; j0 < end; j0 += 32) {
        int m = end - j0; if (m > 32) m = 32;
        int s = 0; float ex = 0.f;
        if (lane < m) {
            s = csr_src[j0 + lane];
            float lg = AS[s] + ad_r;
            lg = (lg > 0.f) ? lg : 0.2f * lg;
            ex = __expf(lg);
        }
#pragma unroll 4
        for (int e = 0; e < m; e++) {
            float a  = __shfl_sync(0xffffffffu, ex, e);
            int   se = __shfl_sync(0xffffffffu, s,  e);
            float2 v = __half22float2(h2h[(size_t)se * 32 + lane]);
            accx = fmaf(v.x, a, accx);
            accy = fmaf(v.y, a, accy);
            den += a;
        }
    }
    float invd = 1.f / (den + 1e-16f);
    float vx = accx * invd + b2[ch];
    float vy = accy * invd + b2[ch + 1];
    vx = (vx > 0.f) ? vx : (__expf(vx) - 1.f);
    vy = (vy > 0.f) ? vy : (__expf(vy) - 1.f);
    int g = batch[w];
    atomicAdd(&pool[g * HIDC + ch],     vx);
    atomicAdd(&pool[g * HIDC + ch + 1], vy);
}

// ---------------- graph node counts: binary search on sorted batch ----------
__global__ void cnt_kernel(const int* __restrict__ batch, float* __restrict__ cnt) {
    int g = threadIdx.x;
    if (g >= NG) return;
    int lo = 0, hi = NN;
    while (lo < hi) { int mid = (lo + hi) >> 1; if (batch[mid] < g) lo = mid + 1; else hi = mid; }
    int a = lo, b = NN;
    while (a < b) { int mid = (a + b) >> 1; if (batch[mid] < g + 1) a = mid + 1; else b = mid; }
    cnt[g] = (float)(a - lo);
}

// ---------------- final FC ----------------------------------------------------
__global__ void final_fc_kernel(const float* __restrict__ pool,
                                const float* __restrict__ cnt,
                                const float* __restrict__ fcw,
                                const float* __restrict__ fcb,
                                float* __restrict__ out) {
    int t = threadIdx.x;
    if (t >= NG * ODIM) return;
    int g = t >> 1, o = t & 1;
    float s = 0.f;
#pragma unroll
    for (int c = 0; c < HIDC; c++) s += pool[g * HIDC + c] * fcw[c * ODIM + o];
    float cc = cnt[g];
    cc = (cc > 1.f) ? cc : 1.f;
    out[g * ODIM + o] = s / cc + fcb[o];
}

// ---------------- launcher ----------------------------------------------------
static inline int nblk(size_t n, int t) { return (int)((n + t - 1) / t); }

extern "C" void kernel_launch(void* const* d_in, const int* in_sizes, int n_in,
                              void* d_out, int out_size) {
    const float* x      = (const float*)d_in[0];
    const float* W1     = (const float*)d_in[1];
    const float* att_s1 = (const float*)d_in[2];
    const float* att_d1 = (const float*)d_in[3];
    const float* b1     = (const float*)d_in[4];
    const float* W2     = (const float*)d_in[5];
    const float* att_s2 = (const float*)d_in[6];
    const float* att_d2 = (const float*)d_in[7];
    const float* b2     = (const float*)d_in[8];
    const float* fcw    = (const float*)d_in[9];
    const float* fcb    = (const float*)d_in[10];
    const int*   ei     = (const int*)d_in[11];
    const int*   batch  = (const int*)d_in[12];
    float* out = (float*)d_out;

    float *AS1, *AD1, *AS2, *AD2, *POOL, *CNT;
    __half *Xh, *W1T, *W2T, *H1h, *H1E, *H2h;
    int *DEG, *ROWPTR, *CURSOR, *CSRC, *PART;
    cudaGetSymbolAddress((void**)&Xh,    g_Xh);
    cudaGetSymbolAddress((void**)&W1T,   g_W1T);
    cudaGetSymbolAddress((void**)&W2T,   g_W2T);
    cudaGetSymbolAddress((void**)&H1h,   g_H1h);
    cudaGetSymbolAddress((void**)&H1E,   g_H1E);
    cudaGetSymbolAddress((void**)&H2h,   g_H2h);
    cudaGetSymbolAddress((void**)&AS1,   g_AS1);
    cudaGetSymbolAddress((void**)&AD1,   g_AD1);
    cudaGetSymbolAddress((void**)&AS2,   g_AS2);
    cudaGetSymbolAddress((void**)&AD2,   g_AD2);
    cudaGetSymbolAddress((void**)&POOL,  g_POOL);
    cudaGetSymbolAddress((void**)&CNT,   g_CNT);
    cudaGetSymbolAddress((void**)&DEG,    g_deg);
    cudaGetSymbolAddress((void**)&ROWPTR, g_rowptr);
    cudaGetSymbolAddress((void**)&CURSOR, g_cursor);
    cudaGetSymbolAddress((void**)&CSRC,   g_csr_src);
    cudaGetSymbolAddress((void**)&PART,   g_part);

    constexpr int SM1 = 2 * (128 * 72 + 128 * 72) * 2;  // 73728
    constexpr int SM2 = 2 * (64 * 72 + 64 * 72) * 2;    // 36864
    cudaFuncSetAttribute((const void*)mma_gemm_fused_kernel<128, 128, 32, NH1, 2>,
                         cudaFuncAttributeMaxDynamicSharedMemorySize, SM1);
    cudaFuncSetAttribute((const void*)mma_gemm_fused_kernel<64, 64, 16, 1, 6>,
                         cudaFuncAttributeMaxDynamicSharedMemorySize, SM2);

    // 1: init   2: prep   3: deg   4: GEMM1 (profiled slot)
    init_kernel<<<nblk(NN, 256), 256>>>(DEG, POOL);
    prep_kernel<<<nblk((size_t)NN * IND, 256), 256>>>(x, W1, W2, Xh, W1T, W2T);
    deg_count_kernel<<<nblk(ETOT, 256), 256>>>(ei, DEG);
    {
        dim3 grid(F1 / 128, (NN + 127) / 128);
        mma_gemm_fused_kernel<128, 128, 32, NH1, 2><<<grid, 256, SM1>>>(
            Xh, W1T, H1h, att_s1, att_d1, AS1, AD1, NN, F1, IND);
    }
    // 5-7: 3-phase scan   8: csr_fill   9: cnt
    scan_a_kernel<<<SCAN_NB, 256>>>(DEG, PART);
    scan_b_kernel<<<1, 256>>>(PART);
    scan_c_kernel<<<SCAN_NB, 256>>>(DEG, PART, ROWPTR, CURSOR);
    csr_fill_kernel<<<nblk(ETOT, 256), 256>>>(ei, CURSOR, CSRC);
    cnt_kernel<<<1, 64>>>(batch, CNT);

    // 10: layer1 gather (fused softmax + bias + elu, fp16 out)
    gather1_kernel<<<NN, 256>>>(ROWPTR, CSRC, AS1, AD1, (const __half2*)H1h, b1, H1E);

    // 11: GEMM2 (fused dots, all fp16)
    {
        dim3 grid(1, (NN + 63) / 64);
        mma_gemm_fused_kernel<64, 64, 16, 1, 6><<<grid, 128, SM2>>>(
            H1E, W2T, H2h, att_s2, att_d2, AS2, AD2, NN, HIDC, F1);
    }

    // 12: layer2 gather (fused softmax + elu + pool)
    gather2_kernel<<<nblk((size_t)NN * 32, 256), 256>>>(
        ROWPTR, CSRC, AS2, AD2, (const __half2*)H2h, b2, batch, POOL);

    // 13: final FC
    final_fc_kernel<<<1, 128>>>(POOL, CNT, fcw, fcb, out);
}

// round 10
// speedup vs baseline: 1.5663x; 1.0300x over previous
#include <cuda_runtime.h>
#include <cuda_fp16.h>
#include <math.h>
#include <stdint.h>
#include <stddef.h>

// Problem constants
#define NN   50000
#define EE   640000
#define ETOT (EE + NN)      // 690000 (self-loops appended)
#define IND  128
#define HIDC 64
#define NH1  8
#define F1   (NH1 * HIDC)   // 512
#define NG   64
#define ODIM 2
#define SCAN_NB ((NN + 255) / 256)   // 196

// ---------------- scratch (device globals; no allocation allowed) ----------
__device__ __half g_Xh  [(size_t)NN * IND];
__device__ __half g_W1T [F1 * IND];
__device__ __half g_W2T [HIDC * F1];
__device__ __half g_H1h [(size_t)NN * F1];
__device__ __half g_H1E [(size_t)NN * F1];
__device__ __half g_H2h [(size_t)NN * HIDC];
__device__ float  g_AS1 [NN * NH1];
__device__ float  g_AD1 [NN * NH1];
__device__ float  g_AS2 [NN];
__device__ float  g_AD2 [NN];
__device__ float  g_POOL[NG * HIDC];
// CSR scratch
__device__ int g_deg   [NN];
__device__ int g_rowptr[NN + 1];
__device__ int g_cursor[NN];
__device__ int g_csr_src[ETOT];
__device__ int g_part  [SCAN_NB];

// ---------------- helpers ---------------------------------------------------
__device__ __forceinline__ void mma_f16(float c[4], const unsigned a[4], const unsigned b[2]) {
    asm volatile(
        "mma.sync.aligned.m16n8k16.row.col.f32.f16.f16.f32 "
        "{%0,%1,%2,%3}, {%4,%5,%6,%7}, {%8,%9}, {%0,%1,%2,%3};"
        : "+f"(c[0]), "+f"(c[1]), "+f"(c[2]), "+f"(c[3])
        : "r"(a[0]), "r"(a[1]), "r"(a[2]), "r"(a[3]), "r"(b[0]), "r"(b[1]));
}

__device__ __forceinline__ void ldsm_x4(unsigned& r0, unsigned& r1, unsigned& r2, unsigned& r3,
                                        uint32_t addr) {
    asm volatile("ldmatrix.sync.aligned.m8n8.x4.shared.b16 {%0,%1,%2,%3}, [%4];"
                 : "=r"(r0), "=r"(r1), "=r"(r2), "=r"(r3) : "r"(addr));
}

__device__ __forceinline__ uint32_t smem_u32(const void* p) {
    return (uint32_t)__cvta_generic_to_shared(p);
}

__device__ __forceinline__ void cp_async16h(__half* dst, const __half* src, bool pred) {
    uint32_t s = (uint32_t)__cvta_generic_to_shared(dst);
    int sz = pred ? 16 : 0;
    asm volatile("cp.async.cg.shared.global [%0], [%1], 16, %2;\n"
                 :: "r"(s), "l"(src), "r"(sz));
}
__device__ __forceinline__ void cp_commit() {
    asm volatile("cp.async.commit_group;\n" ::: "memory");
}
template<int N>
__device__ __forceinline__ void cp_wait() {
    asm volatile("cp.async.wait_group %0;\n" :: "n"(N) : "memory");
}

// ---------------- fused init + fp16 prep ------------------------------------
__global__ void init_prep_kernel(const float* __restrict__ x,
                                 const float* __restrict__ W1,
                                 const float* __restrict__ W2,
                                 __half* __restrict__ xh,
                                 __half* __restrict__ w1t,
                                 __half* __restrict__ w2t,
                                 int* __restrict__ deg,
                                 float* __restrict__ pool) {
    size_t i = (size_t)blockIdx.x * blockDim.x + threadIdx.x;
    if (i < (size_t)NN * IND) xh[i] = __float2half_rn(x[i]);
    if (i < (size_t)F1 * IND) {
        int n = (int)(i / IND), k = (int)(i % IND);
        w1t[i] = __float2half_rn(W1[(size_t)k * F1 + n]);
    }
    if (i < (size_t)HIDC * F1) {
        int n = (int)(i / F1), k = (int)(i % F1);
        w2t[i] = __float2half_rn(W2[(size_t)k * HIDC + n]);
    }
    if (i < NN)        deg[i] = 0;
    if (i < NG * HIDC) pool[i] = 0.f;
}

// ---------------- CSR construction ------------------------------------------
__global__ void deg_count_kernel(const int* __restrict__ ei, int* __restrict__ deg) {
    int e = blockIdx.x * blockDim.x + threadIdx.x;
    if (e >= ETOT) return;
    int d = (e < EE) ? ei[EE + e] : (e - EE);
    atomicAdd(&deg[d], 1);
}

__global__ void scan_a_kernel(const int* __restrict__ deg, int* __restrict__ part) {
    __shared__ int red[256];
    int i = blockIdx.x * 256 + threadIdx.x;
    int v = (i < NN) ? deg[i] : 0;
    red[threadIdx.x] = v;
    __syncthreads();
#pragma unroll
    for (int off = 128; off; off >>= 1) {
        if (threadIdx.x < off) red[threadIdx.x] += red[threadIdx.x + off];
        __syncthreads();
    }
    if (threadIdx.x == 0) part[blockIdx.x] = red[0];
}

// block-local scan + inline reduction of preceding block partials
__global__ void scan_c_kernel(const int* __restrict__ deg, const int* __restrict__ part,
                              int* __restrict__ rowptr, int* __restrict__ cursor) {
    __shared__ int sh[256];
    __shared__ int red[256];
    int t = threadIdx.x;
    int bid = blockIdx.x;
    int pv = (t < bid) ? part[t] : 0;     // SCAN_NB=196 <= 256
    red[t] = pv;
    __syncthreads();
#pragma unroll
    for (int off = 128; off; off >>= 1) {
        if (t < off) red[t] += red[t + off];
        __syncthreads();
    }
    int base = red[0];

    int i = bid * 256 + t;
    int v = (i < NN) ? deg[i] : 0;
    sh[t] = v;
    __syncthreads();
#pragma unroll
    for (int off = 1; off < 256; off <<= 1) {
        int u = (t >= off) ? sh[t - off] : 0;
        __syncthreads();
        sh[t] += u;
        __syncthreads();
    }
    if (i < NN) {
        int excl = base + sh[t] - v;
        rowptr[i] = excl;
        cursor[i] = excl;
    }
    if (i == NN - 1) rowptr[NN] = ETOT;
}

__global__ void csr_fill_kernel(const int* __restrict__ ei, int* __restrict__ cursor,
                                int* __restrict__ csr_src) {
    int e = blockIdx.x * blockDim.x + threadIdx.x;
    if (e >= ETOT) return;
    int s, d;
    if (e < EE) { s = ei[e]; d = ei[EE + e]; } else { s = d = e - EE; }
    int pos = atomicAdd(&cursor[d], 1);
    csr_src[pos] = s;
}

// ---------------- fp16 tensor-core GEMM, cp.async(2-stage) + ldmatrix -------
// Round-8 proven control flow: explicit tail wait.
template<int BM, int BN, int WM, int NH, int MINB>
__global__ void __launch_bounds__((BM / WM) * (BN / 64) * 32, MINB)
mma_gemm_fused_kernel(const __half* __restrict__ A,
                      const __half* __restrict__ Bt,
                      __half* __restrict__ Ch,
                      const float* __restrict__ att_s,
                      const float* __restrict__ att_d,
                      float* __restrict__ AS,
                      float* __restrict__ AD,
                      int M, int N, int K) {
    constexpr int BK = 64;
    constexpr int WN = 64;
    constexpr int WARPS_M = BM / WM;
    constexpr int WARPS_N = BN / 64;
    constexpr int THREADS = WARPS_M * WARPS_N * 32;
    constexpr int MI = WM / 16;
    constexpr int NI = WN / 8;
    constexpr int NJ = NI / 2;
    constexpr int LDA = BK + 8;
    constexpr int LDB = BK + 8;
    constexpr int A_IT = (BM * (BK / 8)) / THREADS;
    constexpr int B_IT = (BN * (BK / 8)) / THREADS;

    extern __shared__ char smem_raw[];
    __half* Asm = (__half*)smem_raw;                                    // [2][BM][LDA]
    __half* Bsm = (__half*)(smem_raw + 2 * BM * LDA * sizeof(__half));

    int tid  = threadIdx.x;
    int wid  = tid >> 5;
    int lane = tid & 31;
    int wm = wid % WARPS_M;
    int wn = wid / WARPS_M;
    int gid = lane >> 2;
    int tg  = lane & 3;

    int blockRow = blockIdx.y * BM;
    int blockCol = blockIdx.x * BN;

    float acc[MI][NI][4];
#pragma unroll
    for (int i = 0; i < MI; i++)
#pragma unroll
        for (int j = 0; j < NI; j++)
#pragma unroll
            for (int v = 0; v < 4; v++) acc[i][j][v] = 0.f;

    const int KT = K / BK;

    auto load_tiles = [&](int kt, int stage) {
        int k0 = kt * BK;
        __half* Ad = Asm + (size_t)stage * BM * LDA;
        __half* Bd = Bsm + (size_t)stage * BN * LDB;
#pragma unroll
        for (int v = 0; v < A_IT; v++) {
            int idx = tid + v * THREADS;
            int r = idx >> 3, c = idx & 7;
            int gr = blockRow + r;
            cp_async16h(Ad + r * LDA + c * 8,
                        A + (size_t)gr * K + k0 + c * 8, gr < M);
        }
#pragma unroll
        for (int v = 0; v < B_IT; v++) {
            int idx = tid + v * THREADS;
            int r = idx >> 3, c = idx & 7;
            cp_async16h(Bd + r * LDB + c * 8,
                        Bt + (size_t)(blockCol + r) * K + k0 + c * 8, true);
        }
    };

    load_tiles(0, 0);
    cp_commit();

    int a_row = wm * WM + (lane & 15);
    int a_col = (lane >> 4) * 8;
    int b_row = wn * WN + (lane & 7) + (lane >> 4) * 8;
    int b_col = ((lane >> 3) & 1) * 8;

    int buf = 0;
    for (int kt = 0; kt < KT; kt++) {
        if (kt + 1 < KT) {
            load_tiles(kt + 1, buf ^ 1);
            cp_commit();
            cp_wait<1>();
        } else {
            cp_wait<0>();
        }
        __syncthreads();

        const __half* Asb = Asm + (size_t)buf * BM * LDA;
        const __half* Bsb = Bsm + (size_t)buf * BN * LDB;
        uint32_t a_addr[MI], b_addr[NJ];
#pragma unroll
        for (int mi = 0; mi < MI; mi++)
            a_addr[mi] = smem_u32(Asb + (size_t)(a_row + mi * 16) * LDA + a_col);
#pragma unroll
        for (int nj = 0; nj < NJ; nj++)
            b_addr[nj] = smem_u32(Bsb + (size_t)(b_row + nj * 16) * LDB + b_col);

#pragma unroll
        for (int kk = 0; kk < BK; kk += 16) {
            unsigned a[MI][4], b[NI][2];
#pragma unroll
            for (int mi = 0; mi < MI; mi++)
                ldsm_x4(a[mi][0], a[mi][1], a[mi][2], a[mi][3], a_addr[mi] + kk * 2);
#pragma unroll
            for (int nj = 0; nj < NJ; nj++)
                ldsm_x4(b[2 * nj][0], b[2 * nj][1], b[2 * nj + 1][0], b[2 * nj + 1][1],
                        b_addr[nj] + kk * 2);
#pragma unroll
            for (int mi = 0; mi < MI; mi++)
#pragma unroll
                for (int ni = 0; ni < NI; ni++)
                    mma_f16(acc[mi][ni], a[mi], b[ni]);
        }
        __syncthreads();
        buf ^= 1;
    }

    // ---- epilogue: fp16 write + fused per-head attention dots ----
    int head = (blockCol >> 6) + wn;
    float asv[NI][2], adv[NI][2];
#pragma unroll
    for (int ni = 0; ni < NI; ni++) {
        int c = head * 64 + ni * 8 + tg * 2;
        asv[ni][0] = att_s[c];     asv[ni][1] = att_s[c + 1];
        adv[ni][0] = att_d[c];     adv[ni][1] = att_d[c + 1];
    }

#pragma unroll
    for (int mi = 0; mi < MI; mi++) {
#pragma unroll
        for (int rh = 0; rh < 2; rh++) {
            int row = blockRow + wm * WM + mi * 16 + gid + rh * 8;
            float ps = 0.f, pd = 0.f;
#pragma unroll
            for (int ni = 0; ni < NI; ni++) {
                float c0 = acc[mi][ni][rh * 2];
                float c1 = acc[mi][ni][rh * 2 + 1];
                ps = fmaf(c0, asv[ni][0], fmaf(c1, asv[ni][1], ps));
                pd = fmaf(c0, adv[ni][0], fmaf(c1, adv[ni][1], pd));
            }
            ps += __shfl_xor_sync(0xffffffffu, ps, 1);
            ps += __shfl_xor_sync(0xffffffffu, ps, 2);
            pd += __shfl_xor_sync(0xffffffffu, pd, 1);
            pd += __shfl_xor_sync(0xffffffffu, pd, 2);
            if (tg == 0 && row < M) {
                AS[row * NH + head] = ps;
                AD[row * NH + head] = pd;
            }
            if (row < M) {
                int col = blockCol + wn * WN;
#pragma unroll
                for (int ni = 0; ni < NI; ni++) {
                    *(__half2*)(Ch + (size_t)row * N + col + ni * 8 + tg * 2) =
                        __floats2half2_rn(acc[mi][ni][rh * 2], acc[mi][ni][rh * 2 + 1]);
                }
            }
        }
    }
}

// ---------------- layer1 fused softmax+gather --------------------------------
__global__ void gather1_kernel(const int* __restrict__ rowptr,
                               const int* __restrict__ csr_src,
                               const float* __restrict__ AS,
                               const float* __restrict__ AD,
                               const __half2* __restrict__ h1h,
                               const float* __restrict__ b1,
                               __half* __restrict__ out) {
    __shared__ int   ssrc[32];
    __shared__ float sex[32][NH1];

    int row = blockIdx.x;
    int tid = threadIdx.x;
    int ch = tid * 2;
    int h = tid >> 5;
    int start = rowptr[row], end = rowptr[row + 1];

    float accx = 0.f, accy = 0.f, den = 0.f;

    for (int j0 = start; j0 < end; j0 += 32) {
        int m = end - j0; if (m > 32) m = 32;
        if (tid < m * NH1) {
            int e = tid >> 3, hh = tid & 7;
            int s = csr_src[j0 + e];
            if (hh == 0) ssrc[e] = s;
            float lg = AS[s * NH1 + hh] + AD[row * NH1 + hh];
            lg = (lg > 0.f) ? lg : 0.2f * lg;
            sex[e][hh] = __expf(lg);
        }
        __syncthreads();
#pragma unroll 4
        for (int e = 0; e < m; e++) {
            int s = ssrc[e];
            float a = sex[e][h];
            float2 v = __half22float2(h1h[(size_t)s * (F1 / 2) + tid]);
            accx = fmaf(v.x, a, accx);
            accy = fmaf(v.y, a, accy);
            den += a;
        }
        __syncthreads();
    }
    float invd = 1.f / (den + 1e-16f);
    float vx = accx * invd + b1[ch];
    float vy = accy * invd + b1[ch + 1];
    vx = (vx > 0.f) ? vx : (__expf(vx) - 1.f);
    vy = (vy > 0.f) ? vy : (__expf(vy) - 1.f);
    *(__half2*)(out + (size_t)row * F1 + ch) = __floats2half2_rn(vx, vy);
}

// ---------------- layer2 fused softmax+gather --------------------------------
__global__ void gather2_kernel(const int* __restrict__ rowptr,
                               const int* __restrict__ csr_src,
                               const float* __restrict__ AS,
                               const float* __restrict__ AD,
                               const __half2* __restrict__ h2h,
                               const float* __restrict__ b2,
                               const int* __restrict__ batch,
                               float* __restrict__ pool) {
    int w = (blockIdx.x * blockDim.x + threadIdx.x) >> 5;
    int lane = threadIdx.x & 31;
    if (w >= NN) return;
    int start = rowptr[w], end = rowptr[w + 1];
    float ad_r = AD[w];
    int ch = lane * 2;
    float accx = 0.f, accy = 0.f, den = 0.f;

    for (int j0 = start; j0 < end; j0 += 32) {
        int m = end - j0; if (m > 32) m = 32;
        int s = 0; float ex = 0.f;
        if (lane < m) {
            s = csr_src[j0 + lane];
            float lg = AS[s] + ad_r;
            lg = (lg > 0.f) ? lg : 0.2f * lg;
            ex = __expf(lg);
        }
#pragma unroll 4
        for (int e = 0; e < m; e++) {
            float a  = __shfl_sync(0xffffffffu, ex, e);
            int   se = __shfl_sync(0xffffffffu, s,  e);
            float2 v = __half22float2(h2h[(size_t)se * 32 + lane]);
            accx = fmaf(v.x, a, accx);
            accy = fmaf(v.y, a, accy);
            den += a;
        }
    }
    float invd = 1.f / (den + 1e-16f);
    float vx = accx * invd + b2[ch];
    float vy = accy * invd + b2[ch + 1];
    vx = (vx > 0.f) ? vx : (__expf(vx) - 1.f);
    vy = (vy > 0.f) ? vy : (__expf(vy) - 1.f);
    int g = batch[w];
    atomicAdd(&pool[g * HIDC + ch],     vx);
    atomicAdd(&pool[g * HIDC + ch + 1], vy);
}

// ---------------- final FC (with inline graph-count binary search) ----------
__global__ void final_fc_kernel(const float* __restrict__ pool,
                                const int* __restrict__ batch,
                                const float* __restrict__ fcw,
                                const float* __restrict__ fcb,
                                float* __restrict__ out) {
    int t = threadIdx.x;
    if (t >= NG * ODIM) return;
    int g = t >> 1, o = t & 1;
    int lo = 0, hi = NN;
    while (lo < hi) { int mid = (lo + hi) >> 1; if (batch[mid] < g) lo = mid + 1; else hi = mid; }
    int a = lo, b = NN;
    while (a < b) { int mid = (a + b) >> 1; if (batch[mid] < g + 1) a = mid + 1; else b = mid; }
    float cc = (float)(a - lo);
    cc = (cc > 1.f) ? cc : 1.f;

    float s = 0.f;
#pragma unroll
    for (int c = 0; c < HIDC; c++) s += pool[g * HIDC + c] * fcw[c * ODIM + o];
    out[g * ODIM + o] = s / cc + fcb[o];
}

// ---------------- launcher ----------------------------------------------------
static inline int nblk(size_t n, int t) { return (int)((n + t - 1) / t); }

extern "C" void kernel_launch(void* const* d_in, const int* in_sizes, int n_in,
                              void* d_out, int out_size) {
    const float* x      = (const float*)d_in[0];
    const float* W1     = (const float*)d_in[1];
    const float* att_s1 = (const float*)d_in[2];
    const float* att_d1 = (const float*)d_in[3];
    const float* b1     = (const float*)d_in[4];
    const float* W2     = (const float*)d_in[5];
    const float* att_s2 = (const float*)d_in[6];
    const float* att_d2 = (const float*)d_in[7];
    const float* b2     = (const float*)d_in[8];
    const float* fcw    = (const float*)d_in[9];
    const float* fcb    = (const float*)d_in[10];
    const int*   ei     = (const int*)d_in[11];
    const int*   batch  = (const int*)d_in[12];
    float* out = (float*)d_out;

    float *AS1, *AD1, *AS2, *AD2, *POOL;
    __half *Xh, *W1T, *W2T, *H1h, *H1E, *H2h;
    int *DEG, *ROWPTR, *CURSOR, *CSRC, *PART;
    cudaGetSymbolAddress((void**)&Xh,    g_Xh);
    cudaGetSymbolAddress((void**)&W1T,   g_W1T);
    cudaGetSymbolAddress((void**)&W2T,   g_W2T);
    cudaGetSymbolAddress((void**)&H1h,   g_H1h);
    cudaGetSymbolAddress((void**)&H1E,   g_H1E);
    cudaGetSymbolAddress((void**)&H2h,   g_H2h);
    cudaGetSymbolAddress((void**)&AS1,   g_AS1);
    cudaGetSymbolAddress((void**)&AD1,   g_AD1);
    cudaGetSymbolAddress((void**)&AS2,   g_AS2);
    cudaGetSymbolAddress((void**)&AD2,   g_AD2);
    cudaGetSymbolAddress((void**)&POOL,  g_POOL);
    cudaGetSymbolAddress((void**)&DEG,    g_deg);
    cudaGetSymbolAddress((void**)&ROWPTR, g_rowptr);
    cudaGetSymbolAddress((void**)&CURSOR, g_cursor);
    cudaGetSymbolAddress((void**)&CSRC,   g_csr_src);
    cudaGetSymbolAddress((void**)&PART,   g_part);

    constexpr int SM1 = 2 * (128 * 72 + 128 * 72) * 2;  // 73728
    constexpr int SM2 = 2 * (64 * 72 + 64 * 72) * 2;    // 36864
    cudaFuncSetAttribute((const void*)mma_gemm_fused_kernel<128, 128, 32, NH1, 2>,
                         cudaFuncAttributeMaxDynamicSharedMemorySize, SM1);
    cudaFuncSetAttribute((const void*)mma_gemm_fused_kernel<64, 64, 16, 1, 6>,
                         cudaFuncAttributeMaxDynamicSharedMemorySize, SM2);

    // 1: init+prep   2: deg   3: scan_a   4: GEMM1 (profiled slot)
    init_prep_kernel<<<nblk((size_t)NN * IND, 256), 256>>>(x, W1, W2, Xh, W1T, W2T, DEG, POOL);
    deg_count_kernel<<<nblk(ETOT, 256), 256>>>(ei, DEG);
    scan_a_kernel<<<SCAN_NB, 256>>>(DEG, PART);
    {
        dim3 grid(F1 / 128, (NN + 127) / 128);
        mma_gemm_fused_kernel<128, 128, 32, NH1, 2><<<grid, 256, SM1>>>(
            Xh, W1T, H1h, att_s1, att_d1, AS1, AD1, NN, F1, IND);
    }
    // 5: scan_c   6: csr_fill
    scan_c_kernel<<<SCAN_NB, 256>>>(DEG, PART, ROWPTR, CURSOR);
    csr_fill_kernel<<<nblk(ETOT, 256), 256>>>(ei, CURSOR, CSRC);

    // 7: layer1 gather
    gather1_kernel<<<NN, 256>>>(ROWPTR, CSRC, AS1, AD1, (const __half2*)H1h, b1, H1E);

    // 8: GEMM2
    {
        dim3 grid(1, (NN + 63) / 64);
        mma_gemm_fused_kernel<64, 64, 16, 1, 6><<<grid, 128, SM2>>>(
            H1E, W2T, H2h, att_s2, att_d2, AS2, AD2, NN, HIDC, F1);
    }

    // 9: layer2 gather
    gather2_kernel<<<nblk((size_t)NN * 32, 256), 256>>>(
        ROWPTR, CSRC, AS2, AD2, (const __half2*)H2h, b2, batch, POOL);

    // 10: final FC (+ inline counts)
    final_fc_kernel<<<1, 128>>>(POOL, batch, fcw, fcb, out);
}

// round 11
// speedup vs baseline: 1.5903x; 1.0154x over previous
#include <cuda_runtime.h>
#include <cuda_fp16.h>
#include <math.h>
#include <stdint.h>
#include <stddef.h>

// Problem constants
#define NN   50000
#define EE   640000
#define ETOT (EE + NN)      // 690000 (self-loops appended)
#define IND  128
#define HIDC 64
#define NH1  8
#define F1   (NH1 * HIDC)   // 512
#define NG   64
#define ODIM 2
#define SCAN_NB ((NN + 255) / 256)   // 196

// ---------------- scratch (device globals; no allocation allowed) ----------
__device__ __half g_Xh  [(size_t)NN * IND];
__device__ __half g_W1T [F1 * IND];
__device__ __half g_W2T [HIDC * F1];
__device__ __half g_H1h [(size_t)NN * F1];
__device__ __half g_H1E [(size_t)NN * F1];
__device__ __half g_H2h [(size_t)NN * HIDC];
__device__ float  g_AS1 [NN * NH1];
__device__ float  g_AD1 [NN * NH1];
__device__ float  g_AS2 [NN];
__device__ float  g_AD2 [NN];
__device__ float  g_POOL[NG * HIDC];
// CSR scratch
__device__ int g_deg   [NN];
__device__ int g_rowptr[NN + 1];
__device__ int g_cursor[NN];
__device__ int g_csr_src[ETOT];
__device__ int g_part  [SCAN_NB];

// ---------------- helpers ---------------------------------------------------
__device__ __forceinline__ void mma_f16(float c[4], const unsigned a[4], const unsigned b[2]) {
    asm volatile(
        "mma.sync.aligned.m16n8k16.row.col.f32.f16.f16.f32 "
        "{%0,%1,%2,%3}, {%4,%5,%6,%7}, {%8,%9}, {%0,%1,%2,%3};"
        : "+f"(c[0]), "+f"(c[1]), "+f"(c[2]), "+f"(c[3])
        : "r"(a[0]), "r"(a[1]), "r"(a[2]), "r"(a[3]), "r"(b[0]), "r"(b[1]));
}

__device__ __forceinline__ void ldsm_x4(unsigned& r0, unsigned& r1, unsigned& r2, unsigned& r3,
                                        uint32_t addr) {
    asm volatile("ldmatrix.sync.aligned.m8n8.x4.shared.b16 {%0,%1,%2,%3}, [%4];"
                 : "=r"(r0), "=r"(r1), "=r"(r2), "=r"(r3) : "r"(addr));
}

__device__ __forceinline__ uint32_t smem_u32(const void* p) {
    return (uint32_t)__cvta_generic_to_shared(p);
}

__device__ __forceinline__ void cp_async16h(__half* dst, const __half* src, bool pred) {
    uint32_t s = (uint32_t)__cvta_generic_to_shared(dst);
    int sz = pred ? 16 : 0;
    asm volatile("cp.async.cg.shared.global [%0], [%1], 16, %2;\n"
                 :: "r"(s), "l"(src), "r"(sz));
}
__device__ __forceinline__ void cp_commit() {
    asm volatile("cp.async.commit_group;\n" ::: "memory");
}
template<int N>
__device__ __forceinline__ void cp_wait() {
    asm volatile("cp.async.wait_group %0;\n" :: "n"(N) : "memory");
}

// ---------------- fp16 prep (pool zero; deg zero moved to side stream) -----
__global__ void init_prep_kernel(const float* __restrict__ x,
                                 const float* __restrict__ W1,
                                 const float* __restrict__ W2,
                                 __half* __restrict__ xh,
                                 __half* __restrict__ w1t,
                                 __half* __restrict__ w2t,
                                 float* __restrict__ pool) {
    size_t i = (size_t)blockIdx.x * blockDim.x + threadIdx.x;
    if (i < (size_t)NN * IND) xh[i] = __float2half_rn(x[i]);
    if (i < (size_t)F1 * IND) {
        int n = (int)(i / IND), k = (int)(i % IND);
        w1t[i] = __float2half_rn(W1[(size_t)k * F1 + n]);
    }
    if (i < (size_t)HIDC * F1) {
        int n = (int)(i / F1), k = (int)(i % F1);
        w2t[i] = __float2half_rn(W2[(size_t)k * HIDC + n]);
    }
    if (i < NG * HIDC) pool[i] = 0.f;
}

__global__ void zero_deg_kernel(int* __restrict__ deg) {
    int i = blockIdx.x * blockDim.x + threadIdx.x;
    if (i < NN) deg[i] = 0;
}

// ---------------- CSR construction ------------------------------------------
__global__ void deg_count_kernel(const int* __restrict__ ei, int* __restrict__ deg) {
    int e = blockIdx.x * blockDim.x + threadIdx.x;
    if (e >= ETOT) return;
    int d = (e < EE) ? ei[EE + e] : (e - EE);
    atomicAdd(&deg[d], 1);
}

__global__ void scan_a_kernel(const int* __restrict__ deg, int* __restrict__ part) {
    __shared__ int red[256];
    int i = blockIdx.x * 256 + threadIdx.x;
    int v = (i < NN) ? deg[i] : 0;
    red[threadIdx.x] = v;
    __syncthreads();
#pragma unroll
    for (int off = 128; off; off >>= 1) {
        if (threadIdx.x < off) red[threadIdx.x] += red[threadIdx.x + off];
        __syncthreads();
    }
    if (threadIdx.x == 0) part[blockIdx.x] = red[0];
}

__global__ void scan_c_kernel(const int* __restrict__ deg, const int* __restrict__ part,
                              int* __restrict__ rowptr, int* __restrict__ cursor) {
    __shared__ int sh[256];
    __shared__ int red[256];
    int t = threadIdx.x;
    int bid = blockIdx.x;
    int pv = (t < bid) ? part[t] : 0;     // SCAN_NB=196 <= 256
    red[t] = pv;
    __syncthreads();
#pragma unroll
    for (int off = 128; off; off >>= 1) {
        if (t < off) red[t] += red[t + off];
        __syncthreads();
    }
    int base = red[0];

    int i = bid * 256 + t;
    int v = (i < NN) ? deg[i] : 0;
    sh[t] = v;
    __syncthreads();
#pragma unroll
    for (int off = 1; off < 256; off <<= 1) {
        int u = (t >= off) ? sh[t - off] : 0;
        __syncthreads();
        sh[t] += u;
        __syncthreads();
    }
    if (i < NN) {
        int excl = base + sh[t] - v;
        rowptr[i] = excl;
        cursor[i] = excl;
    }
    if (i == NN - 1) rowptr[NN] = ETOT;
}

__global__ void csr_fill_kernel(const int* __restrict__ ei, int* __restrict__ cursor,
                                int* __restrict__ csr_src) {
    int e = blockIdx.x * blockDim.x + threadIdx.x;
    if (e >= ETOT) return;
    int s, d;
    if (e < EE) { s = ei[e]; d = ei[EE + e]; } else { s = d = e - EE; }
    int pos = atomicAdd(&cursor[d], 1);
    csr_src[pos] = s;
}

// ---------------- fp16 tensor-core GEMM, cp.async(2-stage) + ldmatrix -------
template<int BM, int BN, int WM, int NH, int MINB>
__global__ void __launch_bounds__((BM / WM) * (BN / 64) * 32, MINB)
mma_gemm_fused_kernel(const __half* __restrict__ A,
                      const __half* __restrict__ Bt,
                      __half* __restrict__ Ch,
                      const float* __restrict__ att_s,
                      const float* __restrict__ att_d,
                      float* __restrict__ AS,
                      float* __restrict__ AD,
                      int M, int N, int K) {
    constexpr int BK = 64;
    constexpr int WN = 64;
    constexpr int WARPS_M = BM / WM;
    constexpr int WARPS_N = BN / 64;
    constexpr int THREADS = WARPS_M * WARPS_N * 32;
    constexpr int MI = WM / 16;
    constexpr int NI = WN / 8;
    constexpr int NJ = NI / 2;
    constexpr int LDA = BK + 8;
    constexpr int LDB = BK + 8;
    constexpr int A_IT = (BM * (BK / 8)) / THREADS;
    constexpr int B_IT = (BN * (BK / 8)) / THREADS;

    extern __shared__ char smem_raw[];
    __half* Asm = (__half*)smem_raw;                                    // [2][BM][LDA]
    __half* Bsm = (__half*)(smem_raw + 2 * BM * LDA * sizeof(__half));

    int tid  = threadIdx.x;
    int wid  = tid >> 5;
    int lane = tid & 31;
    int wm = wid % WARPS_M;
    int wn = wid / WARPS_M;
    int gid = lane >> 2;
    int tg  = lane & 3;

    int blockRow = blockIdx.y * BM;
    int blockCol = blockIdx.x * BN;

    float acc[MI][NI][4];
#pragma unroll
    for (int i = 0; i < MI; i++)
#pragma unroll
        for (int j = 0; j < NI; j++)
#pragma unroll
            for (int v = 0; v < 4; v++) acc[i][j][v] = 0.f;

    const int KT = K / BK;

    auto load_tiles = [&](int kt, int stage) {
        int k0 = kt * BK;
        __half* Ad = Asm + (size_t)stage * BM * LDA;
        __half* Bd = Bsm + (size_t)stage * BN * LDB;
#pragma unroll
        for (int v = 0; v < A_IT; v++) {
            int idx = tid + v * THREADS;
            int r = idx >> 3, c = idx & 7;
            int gr = blockRow + r;
            cp_async16h(Ad + r * LDA + c * 8,
                        A + (size_t)gr * K + k0 + c * 8, gr < M);
        }
#pragma unroll
        for (int v = 0; v < B_IT; v++) {
            int idx = tid + v * THREADS;
            int r = idx >> 3, c = idx & 7;
            cp_async16h(Bd + r * LDB + c * 8,
                        Bt + (size_t)(blockCol + r) * K + k0 + c * 8, true);
        }
    };

    load_tiles(0, 0);
    cp_commit();

    int a_row = wm * WM + (lane & 15);
    int a_col = (lane >> 4) * 8;
    int b_row = wn * WN + (lane & 7) + (lane >> 4) * 8;
    int b_col = ((lane >> 3) & 1) * 8;

    int buf = 0;
    for (int kt = 0; kt < KT; kt++) {
        if (kt + 1 < KT) {
            load_tiles(kt + 1, buf ^ 1);
            cp_commit();
            cp_wait<1>();
        } else {
            cp_wait<0>();
        }
        __syncthreads();

        const __half* Asb = Asm + (size_t)buf * BM * LDA;
        const __half* Bsb = Bsm + (size_t)buf * BN * LDB;
        uint32_t a_addr[MI], b_addr[NJ];
#pragma unroll
        for (int mi = 0; mi < MI; mi++)
            a_addr[mi] = smem_u32(Asb + (size_t)(a_row + mi * 16) * LDA + a_col);
#pragma unroll
        for (int nj = 0; nj < NJ; nj++)
            b_addr[nj] = smem_u32(Bsb + (size_t)(b_row + nj * 16) * LDB + b_col);

#pragma unroll
        for (int kk = 0; kk < BK; kk += 16) {
            unsigned a[MI][4], b[NI][2];
#pragma unroll
            for (int mi = 0; mi < MI; mi++)
                ldsm_x4(a[mi][0], a[mi][1], a[mi][2], a[mi][3], a_addr[mi] + kk * 2);
#pragma unroll
            for (int nj = 0; nj < NJ; nj++)
                ldsm_x4(b[2 * nj][0], b[2 * nj][1], b[2 * nj + 1][0], b[2 * nj + 1][1],
                        b_addr[nj] + kk * 2);
#pragma unroll
            for (int mi = 0; mi < MI; mi++)
#pragma unroll
                for (int ni = 0; ni < NI; ni++)
                    mma_f16(acc[mi][ni], a[mi], b[ni]);
        }
        __syncthreads();
        buf ^= 1;
    }

    // ---- epilogue: fp16 write + fused per-head attention dots ----
    int head = (blockCol >> 6) + wn;
    float asv[NI][2], adv[NI][2];
#pragma unroll
    for (int ni = 0; ni < NI; ni++) {
        int c = head * 64 + ni * 8 + tg * 2;
        asv[ni][0] = att_s[c];     asv[ni][1] = att_s[c + 1];
        adv[ni][0] = att_d[c];     adv[ni][1] = att_d[c + 1];
    }

#pragma unroll
    for (int mi = 0; mi < MI; mi++) {
#pragma unroll
        for (int rh = 0; rh < 2; rh++) {
            int row = blockRow + wm * WM + mi * 16 + gid + rh * 8;
            float ps = 0.f, pd = 0.f;
#pragma unroll
            for (int ni = 0; ni < NI; ni++) {
                float c0 = acc[mi][ni][rh * 2];
                float c1 = acc[mi][ni][rh * 2 + 1];
                ps = fmaf(c0, asv[ni][0], fmaf(c1, asv[ni][1], ps));
                pd = fmaf(c0, adv[ni][0], fmaf(c1, adv[ni][1], pd));
            }
            ps += __shfl_xor_sync(0xffffffffu, ps, 1);
            ps += __shfl_xor_sync(0xffffffffu, ps, 2);
            pd += __shfl_xor_sync(0xffffffffu, pd, 1);
            pd += __shfl_xor_sync(0xffffffffu, pd, 2);
            if (tg == 0 && row < M) {
                AS[row * NH + head] = ps;
                AD[row * NH + head] = pd;
            }
            if (row < M) {
                int col = blockCol + wn * WN;
#pragma unroll
                for (int ni = 0; ni < NI; ni++) {
                    *(__half2*)(Ch + (size_t)row * N + col + ni * 8 + tg * 2) =
                        __floats2half2_rn(acc[mi][ni][rh * 2], acc[mi][ni][rh * 2 + 1]);
                }
            }
        }
    }
}

// ---------------- layer1 fused softmax+gather --------------------------------
__global__ void gather1_kernel(const int* __restrict__ rowptr,
                               const int* __restrict__ csr_src,
                               const float* __restrict__ AS,
                               const float* __restrict__ AD,
                               const __half2* __restrict__ h1h,
                               const float* __restrict__ b1,
                               __half* __restrict__ out) {
    __shared__ int   ssrc[32];
    __shared__ float sex[32][NH1];

    int row = blockIdx.x;
    int tid = threadIdx.x;
    int ch = tid * 2;
    int h = tid >> 5;
    int start = rowptr[row], end = rowptr[row + 1];

    float accx = 0.f, accy = 0.f, den = 0.f;

    for (int j0 = start; j0 < end; j0 += 32) {
        int m = end - j0; if (m > 32) m = 32;
        if (tid < m * NH1) {
            int e = tid >> 3, hh = tid & 7;
            int s = csr_src[j0 + e];
            if (hh == 0) ssrc[e] = s;
            float lg = AS[s * NH1 + hh] + AD[row * NH1 + hh];
            lg = (lg > 0.f) ? lg : 0.2f * lg;
            sex[e][hh] = __expf(lg);
        }
        __syncthreads();
#pragma unroll 4
        for (int e = 0; e < m; e++) {
            int s = ssrc[e];
            float a = sex[e][h];
            float2 v = __half22float2(h1h[(size_t)s * (F1 / 2) + tid]);
            accx = fmaf(v.x, a, accx);
            accy = fmaf(v.y, a, accy);
            den += a;
        }
        __syncthreads();
    }
    float invd = 1.f / (den + 1e-16f);
    float vx = accx * invd + b1[ch];
    float vy = accy * invd + b1[ch + 1];
    vx = (vx > 0.f) ? vx : (__expf(vx) - 1.f);
    vy = (vy > 0.f) ? vy : (__expf(vy) - 1.f);
    *(__half2*)(out + (size_t)row * F1 + ch) = __floats2half2_rn(vx, vy);
}

// ---------------- layer2 fused softmax+gather --------------------------------
__global__ void gather2_kernel(const int* __restrict__ rowptr,
                               const int* __restrict__ csr_src,
                               const float* __restrict__ AS,
                               const float* __restrict__ AD,
                               const __half2* __restrict__ h2h,
                               const float* __restrict__ b2,
                               const int* __restrict__ batch,
                               float* __restrict__ pool) {
    int w = (blockIdx.x * blockDim.x + threadIdx.x) >> 5;
    int lane = threadIdx.x & 31;
    if (w >= NN) return;
    int start = rowptr[w], end = rowptr[w + 1];
    float ad_r = AD[w];
    int ch = lane * 2;
    float accx = 0.f, accy = 0.f, den = 0.f;

    for (int j0 = start; j0 < end; j0 += 32) {
        int m = end - j0; if (m > 32) m = 32;
        int s = 0; float ex = 0.f;
        if (lane < m) {
            s = csr_src[j0 + lane];
            float lg = AS[s] + ad_r;
            lg = (lg > 0.f) ? lg : 0.2f * lg;
            ex = __expf(lg);
        }
#pragma unroll 4
        for (int e = 0; e < m; e++) {
            float a  = __shfl_sync(0xffffffffu, ex, e);
            int   se = __shfl_sync(0xffffffffu, s,  e);
            float2 v = __half22float2(h2h[(size_t)se * 32 + lane]);
            accx = fmaf(v.x, a, accx);
            accy = fmaf(v.y, a, accy);
            den += a;
        }
    }
    float invd = 1.f / (den + 1e-16f);
    float vx = accx * invd + b2[ch];
    float vy = accy * invd + b2[ch + 1];
    vx = (vx > 0.f) ? vx : (__expf(vx) - 1.f);
    vy = (vy > 0.f) ? vy : (__expf(vy) - 1.f);
    int g = batch[w];
    atomicAdd(&pool[g * HIDC + ch],     vx);
    atomicAdd(&pool[g * HIDC + ch + 1], vy);
}

// ---------------- final FC (with inline graph-count binary search) ----------
__global__ void final_fc_kernel(const float* __restrict__ pool,
                                const int* __restrict__ batch,
                                const float* __restrict__ fcw,
                                const float* __restrict__ fcb,
                                float* __restrict__ out) {
    int t = threadIdx.x;
    if (t >= NG * ODIM) return;
    int g = t >> 1, o = t & 1;
    int lo = 0, hi = NN;
    while (lo < hi) { int mid = (lo + hi) >> 1; if (batch[mid] < g) lo = mid + 1; else hi = mid; }
    int a = lo, b = NN;
    while (a < b) { int mid = (a + b) >> 1; if (batch[mid] < g + 1) a = mid + 1; else b = mid; }
    float cc = (float)(a - lo);
    cc = (cc > 1.f) ? cc : 1.f;

    float s = 0.f;
#pragma unroll
    for (int c = 0; c < HIDC; c++) s += pool[g * HIDC + c] * fcw[c * ODIM + o];
    out[g * ODIM + o] = s / cc + fcb[o];
}

// ---------------- launcher ----------------------------------------------------
static inline int nblk(size_t n, int t) { return (int)((n + t - 1) / t); }

extern "C" void kernel_launch(void* const* d_in, const int* in_sizes, int n_in,
                              void* d_out, int out_size) {
    const float* x      = (const float*)d_in[0];
    const float* W1     = (const float*)d_in[1];
    const float* att_s1 = (const float*)d_in[2];
    const float* att_d1 = (const float*)d_in[3];
    const float* b1     = (const float*)d_in[4];
    const float* W2     = (const float*)d_in[5];
    const float* att_s2 = (const float*)d_in[6];
    const float* att_d2 = (const float*)d_in[7];
    const float* b2     = (const float*)d_in[8];
    const float* fcw    = (const float*)d_in[9];
    const float* fcb    = (const float*)d_in[10];
    const int*   ei     = (const int*)d_in[11];
    const int*   batch  = (const int*)d_in[12];
    float* out = (float*)d_out;

    float *AS1, *AD1, *AS2, *AD2, *POOL;
    __half *Xh, *W1T, *W2T, *H1h, *H1E, *H2h;
    int *DEG, *ROWPTR, *CURSOR, *CSRC, *PART;
    cudaGetSymbolAddress((void**)&Xh,    g_Xh);
    cudaGetSymbolAddress((void**)&W1T,   g_W1T);
    cudaGetSymbolAddress((void**)&W2T,   g_W2T);
    cudaGetSymbolAddress((void**)&H1h,   g_H1h);
    cudaGetSymbolAddress((void**)&H1E,   g_H1E);
    cudaGetSymbolAddress((void**)&H2h,   g_H2h);
    cudaGetSymbolAddress((void**)&AS1,   g_AS1);
    cudaGetSymbolAddress((void**)&AD1,   g_AD1);
    cudaGetSymbolAddress((void**)&AS2,   g_AS2);
    cudaGetSymbolAddress((void**)&AD2,   g_AD2);
    cudaGetSymbolAddress((void**)&POOL,  g_POOL);
    cudaGetSymbolAddress((void**)&DEG,    g_deg);
    cudaGetSymbolAddress((void**)&ROWPTR, g_rowptr);
    cudaGetSymbolAddress((void**)&CURSOR, g_cursor);
    cudaGetSymbolAddress((void**)&CSRC,   g_csr_src);
    cudaGetSymbolAddress((void**)&PART,   g_part);

    constexpr int SM1 = 2 * (128 * 72 + 128 * 72) * 2;  // 73728
    constexpr int SM2 = 2 * (64 * 72 + 64 * 72) * 2;    // 36864
    cudaFuncSetAttribute((const void*)mma_gemm_fused_kernel<128, 128, 32, NH1, 2>,
                         cudaFuncAttributeMaxDynamicSharedMemorySize, SM1);
    cudaFuncSetAttribute((const void*)mma_gemm_fused_kernel<64, 64, 16, 1, 6>,
                         cudaFuncAttributeMaxDynamicSharedMemorySize, SM2);

    // side stream + fork/join events (created once; identical work every call)
    static cudaStream_t sB = nullptr;
    static cudaEvent_t  eFork = nullptr, eJoin = nullptr;
    if (sB == nullptr) {
        cudaStreamCreateWithFlags(&sB, cudaStreamNonBlocking);
        cudaEventCreateWithFlags(&eFork, cudaEventDisableTiming);
        cudaEventCreateWithFlags(&eJoin, cudaEventDisableTiming);
    }

    // ---- fork: CSR chain on side stream, prep+GEMM1 on main stream ----
    cudaEventRecord(eFork, 0);
    cudaStreamWaitEvent(sB, eFork, 0);

    zero_deg_kernel<<<nblk(NN, 256), 256, 0, sB>>>(DEG);
    deg_count_kernel<<<nblk(ETOT, 256), 256, 0, sB>>>(ei, DEG);
    scan_a_kernel<<<SCAN_NB, 256, 0, sB>>>(DEG, PART);
    scan_c_kernel<<<SCAN_NB, 256, 0, sB>>>(DEG, PART, ROWPTR, CURSOR);
    csr_fill_kernel<<<nblk(ETOT, 256), 256, 0, sB>>>(ei, CURSOR, CSRC);
    cudaEventRecord(eJoin, sB);

    init_prep_kernel<<<nblk((size_t)NN * IND, 256), 256>>>(x, W1, W2, Xh, W1T, W2T, POOL);
    {
        dim3 grid(F1 / 128, (NN + 127) / 128);
        mma_gemm_fused_kernel<128, 128, 32, NH1, 2><<<grid, 256, SM1>>>(
            Xh, W1T, H1h, att_s1, att_d1, AS1, AD1, NN, F1, IND);
    }

    // ---- join ----
    cudaStreamWaitEvent(0, eJoin, 0);

    // layer1 gather
    gather1_kernel<<<NN, 256>>>(ROWPTR, CSRC, AS1, AD1, (const __half2*)H1h, b1, H1E);

    // GEMM2
    {
        dim3 grid(1, (NN + 63) / 64);
        mma_gemm_fused_kernel<64, 64, 16, 1, 6><<<grid, 128, SM2>>>(
            H1E, W2T, H2h, att_s2, att_d2, AS2, AD2, NN, HIDC, F1);
    }

    // layer2 gather
    gather2_kernel<<<nblk((size_t)NN * 32, 256), 256>>>(
        ROWPTR, CSRC, AS2, AD2, (const __half2*)H2h, b2, batch, POOL);

    // final FC (+ inline counts)
    final_fc_kernel<<<1, 128>>>(POOL, batch, fcw, fcb, out);
}

// round 12
// speedup vs baseline: 1.9187x; 1.2065x over previous
#include <cuda_runtime.h>
#include <cuda_fp16.h>
#include <math.h>
#include <stdint.h>
#include <stddef.h>

// Problem constants
#define NN   50000
#define EE   640000
#define ETOT (EE + NN)      // 690000 (self-loops appended)
#define IND  128
#define HIDC 64
#define NH1  8
#define F1   (NH1 * HIDC)   // 512
#define NG   64
#define ODIM 2
#define SCAN_NB ((NN + 255) / 256)   // 196

// ---------------- scratch (device globals; no allocation allowed) ----------
__device__ __half g_Xh  [(size_t)NN * IND];
__device__ __half g_W1T [F1 * IND];
__device__ __half g_W2T [HIDC * F1];
__device__ __half g_H1h [(size_t)NN * F1];
__device__ __half g_H1E [(size_t)NN * F1];
__device__ __half g_H2h [(size_t)NN * HIDC];
__device__ float  g_AS1 [NN * NH1];
__device__ float  g_AD1 [NN * NH1];
__device__ float  g_AS2 [NN];
__device__ float  g_AD2 [NN];
__device__ float  g_POOL[NG * HIDC];
// CSR scratch
__device__ int g_deg   [NN];
__device__ int g_rowptr[NN + 1];
__device__ int g_cursor[NN];
__device__ int g_csr_src[ETOT];
__device__ int g_part  [SCAN_NB];

// ---------------- helpers ---------------------------------------------------
__device__ __forceinline__ void mma_f16(float c[4], const unsigned a[4], const unsigned b[2]) {
    asm volatile(
        "mma.sync.aligned.m16n8k16.row.col.f32.f16.f16.f32 "
        "{%0,%1,%2,%3}, {%4,%5,%6,%7}, {%8,%9}, {%0,%1,%2,%3};"
        : "+f"(c[0]), "+f"(c[1]), "+f"(c[2]), "+f"(c[3])
        : "r"(a[0]), "r"(a[1]), "r"(a[2]), "r"(a[3]), "r"(b[0]), "r"(b[1]));
}

__device__ __forceinline__ void ldsm_x4(unsigned& r0, unsigned& r1, unsigned& r2, unsigned& r3,
                                        uint32_t addr) {
    asm volatile("ldmatrix.sync.aligned.m8n8.x4.shared.b16 {%0,%1,%2,%3}, [%4];"
                 : "=r"(r0), "=r"(r1), "=r"(r2), "=r"(r3) : "r"(addr));
}

__device__ __forceinline__ uint32_t smem_u32(const void* p) {
    return (uint32_t)__cvta_generic_to_shared(p);
}

__device__ __forceinline__ void cp_async16h(__half* dst, const __half* src, bool pred) {
    uint32_t s = (uint32_t)__cvta_generic_to_shared(dst);
    int sz = pred ? 16 : 0;
    asm volatile("cp.async.cg.shared.global [%0], [%1], 16, %2;\n"
                 :: "r"(s), "l"(src), "r"(sz));
}
__device__ __forceinline__ void cp_commit() {
    asm volatile("cp.async.commit_group;\n" ::: "memory");
}
template<int N>
__device__ __forceinline__ void cp_wait() {
    asm volatile("cp.async.wait_group %0;\n" :: "n"(N) : "memory");
}

// ---------------- fp16 prep (pool zero; deg zero on side stream) ------------
__global__ void init_prep_kernel(const float* __restrict__ x,
                                 const float* __restrict__ W1,
                                 const float* __restrict__ W2,
                                 __half* __restrict__ xh,
                                 __half* __restrict__ w1t,
                                 __half* __restrict__ w2t,
                                 float* __restrict__ pool) {
    size_t i = (size_t)blockIdx.x * blockDim.x + threadIdx.x;
    if (i < (size_t)NN * IND) xh[i] = __float2half_rn(x[i]);
    if (i < (size_t)F1 * IND) {
        int n = (int)(i / IND), k = (int)(i % IND);
        w1t[i] = __float2half_rn(W1[(size_t)k * F1 + n]);
    }
    if (i < (size_t)HIDC * F1) {
        int n = (int)(i / F1), k = (int)(i % F1);
        w2t[i] = __float2half_rn(W2[(size_t)k * HIDC + n]);
    }
    if (i < NG * HIDC) pool[i] = 0.f;
}

__global__ void zero_deg_kernel(int* __restrict__ deg) {
    int i = blockIdx.x * blockDim.x + threadIdx.x;
    if (i < NN) deg[i] = 0;
}

// ---------------- CSR construction ------------------------------------------
__global__ void deg_count_kernel(const int* __restrict__ ei, int* __restrict__ deg) {
    int e = blockIdx.x * blockDim.x + threadIdx.x;
    if (e >= ETOT) return;
    int d = (e < EE) ? ei[EE + e] : (e - EE);
    atomicAdd(&deg[d], 1);
}

__global__ void scan_a_kernel(const int* __restrict__ deg, int* __restrict__ part) {
    __shared__ int red[256];
    int i = blockIdx.x * 256 + threadIdx.x;
    int v = (i < NN) ? deg[i] : 0;
    red[threadIdx.x] = v;
    __syncthreads();
#pragma unroll
    for (int off = 128; off; off >>= 1) {
        if (threadIdx.x < off) red[threadIdx.x] += red[threadIdx.x + off];
        __syncthreads();
    }
    if (threadIdx.x == 0) part[blockIdx.x] = red[0];
}

__global__ void scan_c_kernel(const int* __restrict__ deg, const int* __restrict__ part,
                              int* __restrict__ rowptr, int* __restrict__ cursor) {
    __shared__ int sh[256];
    __shared__ int red[256];
    int t = threadIdx.x;
    int bid = blockIdx.x;
    int pv = (t < bid) ? part[t] : 0;     // SCAN_NB=196 <= 256
    red[t] = pv;
    __syncthreads();
#pragma unroll
    for (int off = 128; off; off >>= 1) {
        if (t < off) red[t] += red[t + off];
        __syncthreads();
    }
    int base = red[0];

    int i = bid * 256 + t;
    int v = (i < NN) ? deg[i] : 0;
    sh[t] = v;
    __syncthreads();
#pragma unroll
    for (int off = 1; off < 256; off <<= 1) {
        int u = (t >= off) ? sh[t - off] : 0;
        __syncthreads();
        sh[t] += u;
        __syncthreads();
    }
    if (i < NN) {
        int excl = base + sh[t] - v;
        rowptr[i] = excl;
        cursor[i] = excl;
    }
    if (i == NN - 1) rowptr[NN] = ETOT;
}

__global__ void csr_fill_kernel(const int* __restrict__ ei, int* __restrict__ cursor,
                                int* __restrict__ csr_src) {
    int e = blockIdx.x * blockDim.x + threadIdx.x;
    if (e >= ETOT) return;
    int s, d;
    if (e < EE) { s = ei[e]; d = ei[EE + e]; } else { s = d = e - EE; }
    int pos = atomicAdd(&cursor[d], 1);
    csr_src[pos] = s;
}

// ---------------- fp16 tensor-core GEMM, cp.async(2-stage) + ldmatrix -------
template<int BM, int BN, int WM, int NH, int MINB>
__global__ void __launch_bounds__((BM / WM) * (BN / 64) * 32, MINB)
mma_gemm_fused_kernel(const __half* __restrict__ A,
                      const __half* __restrict__ Bt,
                      __half* __restrict__ Ch,
                      const float* __restrict__ att_s,
                      const float* __restrict__ att_d,
                      float* __restrict__ AS,
                      float* __restrict__ AD,
                      int M, int N, int K) {
    constexpr int BK = 64;
    constexpr int WN = 64;
    constexpr int WARPS_M = BM / WM;
    constexpr int WARPS_N = BN / 64;
    constexpr int THREADS = WARPS_M * WARPS_N * 32;
    constexpr int MI = WM / 16;
    constexpr int NI = WN / 8;
    constexpr int NJ = NI / 2;
    constexpr int LDA = BK + 8;
    constexpr int LDB = BK + 8;
    constexpr int A_IT = (BM * (BK / 8)) / THREADS;
    constexpr int B_IT = (BN * (BK / 8)) / THREADS;

    extern __shared__ char smem_raw[];
    __half* Asm = (__half*)smem_raw;                                    // [2][BM][LDA]
    __half* Bsm = (__half*)(smem_raw + 2 * BM * LDA * sizeof(__half));

    int tid  = threadIdx.x;
    int wid  = tid >> 5;
    int lane = tid & 31;
    int wm = wid % WARPS_M;
    int wn = wid / WARPS_M;
    int gid = lane >> 2;
    int tg  = lane & 3;

    int blockRow = blockIdx.y * BM;
    int blockCol = blockIdx.x * BN;

    float acc[MI][NI][4];
#pragma unroll
    for (int i = 0; i < MI; i++)
#pragma unroll
        for (int j = 0; j < NI; j++)
#pragma unroll
            for (int v = 0; v < 4; v++) acc[i][j][v] = 0.f;

    const int KT = K / BK;

    auto load_tiles = [&](int kt, int stage) {
        int k0 = kt * BK;
        __half* Ad = Asm + (size_t)stage * BM * LDA;
        __half* Bd = Bsm + (size_t)stage * BN * LDB;
#pragma unroll
        for (int v = 0; v < A_IT; v++) {
            int idx = tid + v * THREADS;
            int r = idx >> 3, c = idx & 7;
            int gr = blockRow + r;
            cp_async16h(Ad + r * LDA + c * 8,
                        A + (size_t)gr * K + k0 + c * 8, gr < M);
        }
#pragma unroll
        for (int v = 0; v < B_IT; v++) {
            int idx = tid + v * THREADS;
            int r = idx >> 3, c = idx & 7;
            cp_async16h(Bd + r * LDB + c * 8,
                        Bt + (size_t)(blockCol + r) * K + k0 + c * 8, true);
        }
    };

    load_tiles(0, 0);
    cp_commit();

    int a_row = wm * WM + (lane & 15);
    int a_col = (lane >> 4) * 8;
    int b_row = wn * WN + (lane & 7) + (lane >> 4) * 8;
    int b_col = ((lane >> 3) & 1) * 8;

    int buf = 0;
    for (int kt = 0; kt < KT; kt++) {
        if (kt + 1 < KT) {
            load_tiles(kt + 1, buf ^ 1);
            cp_commit();
            cp_wait<1>();
        } else {
            cp_wait<0>();
        }
        __syncthreads();

        const __half* Asb = Asm + (size_t)buf * BM * LDA;
        const __half* Bsb = Bsm + (size_t)buf * BN * LDB;
        uint32_t a_addr[MI], b_addr[NJ];
#pragma unroll
        for (int mi = 0; mi < MI; mi++)
            a_addr[mi] = smem_u32(Asb + (size_t)(a_row + mi * 16) * LDA + a_col);
#pragma unroll
        for (int nj = 0; nj < NJ; nj++)
            b_addr[nj] = smem_u32(Bsb + (size_t)(b_row + nj * 16) * LDB + b_col);

#pragma unroll
        for (int kk = 0; kk < BK; kk += 16) {
            unsigned a[MI][4], b[NI][2];
#pragma unroll
            for (int mi = 0; mi < MI; mi++)
                ldsm_x4(a[mi][0], a[mi][1], a[mi][2], a[mi][3], a_addr[mi] + kk * 2);
#pragma unroll
            for (int nj = 0; nj < NJ; nj++)
                ldsm_x4(b[2 * nj][0], b[2 * nj][1], b[2 * nj + 1][0], b[2 * nj + 1][1],
                        b_addr[nj] + kk * 2);
#pragma unroll
            for (int mi = 0; mi < MI; mi++)
#pragma unroll
                for (int ni = 0; ni < NI; ni++)
                    mma_f16(acc[mi][ni], a[mi], b[ni]);
        }
        __syncthreads();
        buf ^= 1;
    }

    // ---- epilogue: fp16 write + fused per-head attention dots ----
    int head = (blockCol >> 6) + wn;
    float asv[NI][2], adv[NI][2];
#pragma unroll
    for (int ni = 0; ni < NI; ni++) {
        int c = head * 64 + ni * 8 + tg * 2;
        asv[ni][0] = att_s[c];     asv[ni][1] = att_s[c + 1];
        adv[ni][0] = att_d[c];     adv[ni][1] = att_d[c + 1];
    }

#pragma unroll
    for (int mi = 0; mi < MI; mi++) {
#pragma unroll
        for (int rh = 0; rh < 2; rh++) {
            int row = blockRow + wm * WM + mi * 16 + gid + rh * 8;
            float ps = 0.f, pd = 0.f;
#pragma unroll
            for (int ni = 0; ni < NI; ni++) {
                float c0 = acc[mi][ni][rh * 2];
                float c1 = acc[mi][ni][rh * 2 + 1];
                ps = fmaf(c0, asv[ni][0], fmaf(c1, asv[ni][1], ps));
                pd = fmaf(c0, adv[ni][0], fmaf(c1, adv[ni][1], pd));
            }
            ps += __shfl_xor_sync(0xffffffffu, ps, 1);
            ps += __shfl_xor_sync(0xffffffffu, ps, 2);
            pd += __shfl_xor_sync(0xffffffffu, pd, 1);
            pd += __shfl_xor_sync(0xffffffffu, pd, 2);
            if (tg == 0 && row < M) {
                AS[row * NH + head] = ps;
                AD[row * NH + head] = pd;
            }
            if (row < M) {
                int col = blockCol + wn * WN;
#pragma unroll
                for (int ni = 0; ni < NI; ni++) {
                    *(__half2*)(Ch + (size_t)row * N + col + ni * 8 + tg * 2) =
                        __floats2half2_rn(acc[mi][ni][rh * 2], acc[mi][ni][rh * 2 + 1]);
                }
            }
        }
    }
}

// ---------------- layer1 fused softmax+gather --------------------------------
// 128 threads per dst row; thread owns 4 channels (one 8B uint2 load/edge).
// Edge chunk = 16 (staging: 16 edges x 8 heads = 128 threads).
__global__ void gather1_kernel(const int* __restrict__ rowptr,
                               const int* __restrict__ csr_src,
                               const float* __restrict__ AS,
                               const float* __restrict__ AD,
                               const uint2* __restrict__ h1h,
                               const float* __restrict__ b1,
                               __half* __restrict__ out) {
    __shared__ int   ssrc[16];
    __shared__ float sex[16][NH1];
    __shared__ float sad[NH1];

    int row = blockIdx.x;
    int tid = threadIdx.x;          // 0..127
    int head = tid >> 4;            // channels 4*tid.., head = 4*tid/64
    int start = rowptr[row], end = rowptr[row + 1];

    if (tid < NH1) sad[tid] = AD[row * NH1 + tid];
    __syncthreads();

    float a0 = 0.f, a1 = 0.f, a2 = 0.f, a3 = 0.f, den = 0.f;

    for (int j0 = start; j0 < end; j0 += 16) {
        int m = end - j0; if (m > 16) m = 16;
        if (tid < m * NH1) {
            int e = tid >> 3, hh = tid & 7;
            int s = csr_src[j0 + e];
            if (hh == 0) ssrc[e] = s;
            float lg = AS[s * NH1 + hh] + sad[hh];
            lg = (lg > 0.f) ? lg : 0.2f * lg;
            sex[e][hh] = __expf(lg);
        }
        __syncthreads();
#pragma unroll 4
        for (int e = 0; e < m; e++) {
            int s = ssrc[e];
            float a = sex[e][head];
            uint2 u = h1h[(size_t)s * (F1 / 4) + tid];
            float2 f0 = __half22float2(*(__half2*)&u.x);
            float2 f1 = __half22float2(*(__half2*)&u.y);
            a0 = fmaf(f0.x, a, a0);
            a1 = fmaf(f0.y, a, a1);
            a2 = fmaf(f1.x, a, a2);
            a3 = fmaf(f1.y, a, a3);
            den += a;
        }
        __syncthreads();
    }
    float invd = 1.f / (den + 1e-16f);
    int ch = tid * 4;
    float v0 = a0 * invd + b1[ch];
    float v1 = a1 * invd + b1[ch + 1];
    float v2 = a2 * invd + b1[ch + 2];
    float v3 = a3 * invd + b1[ch + 3];
    v0 = (v0 > 0.f) ? v0 : (__expf(v0) - 1.f);
    v1 = (v1 > 0.f) ? v1 : (__expf(v1) - 1.f);
    v2 = (v2 > 0.f) ? v2 : (__expf(v2) - 1.f);
    v3 = (v3 > 0.f) ? v3 : (__expf(v3) - 1.f);
    uint2 o;
    *(__half2*)&o.x = __floats2half2_rn(v0, v1);
    *(__half2*)&o.y = __floats2half2_rn(v2, v3);
    *(uint2*)(out + (size_t)row * F1 + ch) = o;
}

// ---------------- layer2 fused softmax+gather --------------------------------
__global__ void gather2_kernel(const int* __restrict__ rowptr,
                               const int* __restrict__ csr_src,
                               const float* __restrict__ AS,
                               const float* __restrict__ AD,
                               const __half2* __restrict__ h2h,
                               const float* __restrict__ b2,
                               const int* __restrict__ batch,
                               float* __restrict__ pool) {
    int w = (blockIdx.x * blockDim.x + threadIdx.x) >> 5;
    int lane = threadIdx.x & 31;
    if (w >= NN) return;
    int start = rowptr[w], end = rowptr[w + 1];
    float ad_r = AD[w];
    int ch = lane * 2;
    float accx = 0.f, accy = 0.f, den = 0.f;

    for (int j0 = start; j0 < end; j0 += 32) {
        int m = end - j0; if (m > 32) m = 32;
        int s = 0; float ex = 0.f;
        if (lane < m) {
            s = csr_src[j0 + lane];
            float lg = AS[s] + ad_r;
            lg = (lg > 0.f) ? lg : 0.2f * lg;
            ex = __expf(lg);
        }
#pragma unroll 4
        for (int e = 0; e < m; e++) {
            float a  = __shfl_sync(0xffffffffu, ex, e);
            int   se = __shfl_sync(0xffffffffu, s,  e);
            float2 v = __half22float2(h2h[(size_t)se * 32 + lane]);
            accx = fmaf(v.x, a, accx);
            accy = fmaf(v.y, a, accy);
            den += a;
        }
    }
    float invd = 1.f / (den + 1e-16f);
    float vx = accx * invd + b2[ch];
    float vy = accy * invd + b2[ch + 1];
    vx = (vx > 0.f) ? vx : (__expf(vx) - 1.f);
    vy = (vy > 0.f) ? vy : (__expf(vy) - 1.f);
    int g = batch[w];
    atomicAdd(&pool[g * HIDC + ch],     vx);
    atomicAdd(&pool[g * HIDC + ch + 1], vy);
}

// ---------------- final FC (with inline graph-count binary search) ----------
__global__ void final_fc_kernel(const float* __restrict__ pool,
                                const int* __restrict__ batch,
                                const float* __restrict__ fcw,
                                const float* __restrict__ fcb,
                                float* __restrict__ out) {
    int t = threadIdx.x;
    if (t >= NG * ODIM) return;
    int g = t >> 1, o = t & 1;
    int lo = 0, hi = NN;
    while (lo < hi) { int mid = (lo + hi) >> 1; if (batch[mid] < g) lo = mid + 1; else hi = mid; }
    int a = lo, b = NN;
    while (a < b) { int mid = (a + b) >> 1; if (batch[mid] < g + 1) a = mid + 1; else b = mid; }
    float cc = (float)(a - lo);
    cc = (cc > 1.f) ? cc : 1.f;

    float s = 0.f;
#pragma unroll
    for (int c = 0; c < HIDC; c++) s += pool[g * HIDC + c] * fcw[c * ODIM + o];
    out[g * ODIM + o] = s / cc + fcb[o];
}

// ---------------- launcher ----------------------------------------------------
static inline int nblk(size_t n, int t) { return (int)((n + t - 1) / t); }

extern "C" void kernel_launch(void* const* d_in, const int* in_sizes, int n_in,
                              void* d_out, int out_size) {
    const float* x      = (const float*)d_in[0];
    const float* W1     = (const float*)d_in[1];
    const float* att_s1 = (const float*)d_in[2];
    const float* att_d1 = (const float*)d_in[3];
    const float* b1     = (const float*)d_in[4];
    const float* W2     = (const float*)d_in[5];
    const float* att_s2 = (const float*)d_in[6];
    const float* att_d2 = (const float*)d_in[7];
    const float* b2     = (const float*)d_in[8];
    const float* fcw    = (const float*)d_in[9];
    const float* fcb    = (const float*)d_in[10];
    const int*   ei     = (const int*)d_in[11];
    const int*   batch  = (const int*)d_in[12];
    float* out = (float*)d_out;

    float *AS1, *AD1, *AS2, *AD2, *POOL;
    __half *Xh, *W1T, *W2T, *H1h, *H1E, *H2h;
    int *DEG, *ROWPTR, *CURSOR, *CSRC, *PART;
    cudaGetSymbolAddress((void**)&Xh,    g_Xh);
    cudaGetSymbolAddress((void**)&W1T,   g_W1T);
    cudaGetSymbolAddress((void**)&W2T,   g_W2T);
    cudaGetSymbolAddress((void**)&H1h,   g_H1h);
    cudaGetSymbolAddress((void**)&H1E,   g_H1E);
    cudaGetSymbolAddress((void**)&H2h,   g_H2h);
    cudaGetSymbolAddress((void**)&AS1,   g_AS1);
    cudaGetSymbolAddress((void**)&AD1,   g_AD1);
    cudaGetSymbolAddress((void**)&AS2,   g_AS2);
    cudaGetSymbolAddress((void**)&AD2,   g_AD2);
    cudaGetSymbolAddress((void**)&POOL,  g_POOL);
    cudaGetSymbolAddress((void**)&DEG,    g_deg);
    cudaGetSymbolAddress((void**)&ROWPTR, g_rowptr);
    cudaGetSymbolAddress((void**)&CURSOR, g_cursor);
    cudaGetSymbolAddress((void**)&CSRC,   g_csr_src);
    cudaGetSymbolAddress((void**)&PART,   g_part);

    constexpr int SM1 = 2 * (128 * 72 + 128 * 72) * 2;  // 73728
    constexpr int SM2 = 2 * (64 * 72 + 64 * 72) * 2;    // 36864
    cudaFuncSetAttribute((const void*)mma_gemm_fused_kernel<128, 128, 32, NH1, 2>,
                         cudaFuncAttributeMaxDynamicSharedMemorySize, SM1);
    cudaFuncSetAttribute((const void*)mma_gemm_fused_kernel<64, 64, 16, 1, 6>,
                         cudaFuncAttributeMaxDynamicSharedMemorySize, SM2);

    // side stream + fork/join events (created once; identical work every call)
    static cudaStream_t sB = nullptr;
    static cudaEvent_t  eFork = nullptr, eJoin = nullptr;
    if (sB == nullptr) {
        cudaStreamCreateWithFlags(&sB, cudaStreamNonBlocking);
        cudaEventCreateWithFlags(&eFork, cudaEventDisableTiming);
        cudaEventCreateWithFlags(&eJoin, cudaEventDisableTiming);
    }

    // ---- fork: CSR chain on side stream, prep+GEMM1 on main stream ----
    cudaEventRecord(eFork, 0);
    cudaStreamWaitEvent(sB, eFork, 0);

    zero_deg_kernel<<<nblk(NN, 256), 256, 0, sB>>>(DEG);
    deg_count_kernel<<<nblk(ETOT, 256), 256, 0, sB>>>(ei, DEG);
    scan_a_kernel<<<SCAN_NB, 256, 0, sB>>>(DEG, PART);
    scan_c_kernel<<<SCAN_NB, 256, 0, sB>>>(DEG, PART, ROWPTR, CURSOR);
    csr_fill_kernel<<<nblk(ETOT, 256), 256, 0, sB>>>(ei, CURSOR, CSRC);
    cudaEventRecord(eJoin, sB);

    init_prep_kernel<<<nblk((size_t)NN * IND, 256), 256>>>(x, W1, W2, Xh, W1T, W2T, POOL);
    {
        dim3 grid(F1 / 128, (NN + 127) / 128);
        mma_gemm_fused_kernel<128, 128, 32, NH1, 2><<<grid, 256, SM1>>>(
            Xh, W1T, H1h, att_s1, att_d1, AS1, AD1, NN, F1, IND);
    }

    // ---- join ----
    cudaStreamWaitEvent(0, eJoin, 0);

    // layer1 gather (128 threads/row, uint2 loads)
    gather1_kernel<<<NN, 128>>>(ROWPTR, CSRC, AS1, AD1, (const uint2*)H1h, b1, H1E);

    // GEMM2
    {
        dim3 grid(1, (NN + 63) / 64);
        mma_gemm_fused_kernel<64, 64, 16, 1, 6><<<grid, 128, SM2>>>(
            H1E, W2T, H2h, att_s2, att_d2, AS2, AD2, NN, HIDC, F1);
    }

    // layer2 gather
    gather2_kernel<<<nblk((size_t)NN * 32, 256), 256>>>(
        ROWPTR, CSRC, AS2, AD2, (const __half2*)H2h, b2, batch, POOL);

    // final FC (+ inline counts)
    final_fc_kernel<<<1, 128>>>(POOL, batch, fcw, fcb, out);
}

// round 13
// speedup vs baseline: 2.0850x; 1.0867x over previous
#include <cuda_runtime.h>
#include <cuda_fp16.h>
#include <math.h>
#include <stdint.h>
#include <stddef.h>

// Problem constants
#define NN   50000
#define EE   640000
#define ETOT (EE + NN)      // 690000 (self-loops appended)
#define IND  128
#define HIDC 64
#define NH1  8
#define F1   (NH1 * HIDC)   // 512
#define NG   64
#define ODIM 2
#define SCAN_NB ((NN + 255) / 256)   // 196

// ---------------- scratch (device globals; no allocation allowed) ----------
__device__ __half g_Xh  [(size_t)NN * IND];
__device__ __half g_W1T [F1 * IND];
__device__ __half g_W2T [HIDC * F1];
__device__ __half g_H1h [(size_t)NN * F1];
__device__ __half g_H1E [(size_t)NN * F1];
__device__ __half g_H2h [(size_t)NN * HIDC];
__device__ float  g_AS1 [NN * NH1];
__device__ float  g_AD1 [NN * NH1];
__device__ float  g_AS2 [NN];
__device__ float  g_AD2 [NN];
__device__ float  g_POOL[NG * HIDC];
// CSR scratch
__device__ int g_deg   [NN];
__device__ int g_rowptr[NN + 1];
__device__ int g_cursor[NN];
__device__ int g_csr_src[ETOT];
__device__ int g_part  [SCAN_NB];

// ---------------- helpers ---------------------------------------------------
__device__ __forceinline__ void mma_f16(float c[4], const unsigned a[4], const unsigned b[2]) {
    asm volatile(
        "mma.sync.aligned.m16n8k16.row.col.f32.f16.f16.f32 "
        "{%0,%1,%2,%3}, {%4,%5,%6,%7}, {%8,%9}, {%0,%1,%2,%3};"
        : "+f"(c[0]), "+f"(c[1]), "+f"(c[2]), "+f"(c[3])
        : "r"(a[0]), "r"(a[1]), "r"(a[2]), "r"(a[3]), "r"(b[0]), "r"(b[1]));
}

__device__ __forceinline__ void ldsm_x4(unsigned& r0, unsigned& r1, unsigned& r2, unsigned& r3,
                                        uint32_t addr) {
    asm volatile("ldmatrix.sync.aligned.m8n8.x4.shared.b16 {%0,%1,%2,%3}, [%4];"
                 : "=r"(r0), "=r"(r1), "=r"(r2), "=r"(r3) : "r"(addr));
}

__device__ __forceinline__ uint32_t smem_u32(const void* p) {
    return (uint32_t)__cvta_generic_to_shared(p);
}

__device__ __forceinline__ void cp_async16h(__half* dst, const __half* src, bool pred) {
    uint32_t s = (uint32_t)__cvta_generic_to_shared(dst);
    int sz = pred ? 16 : 0;
    asm volatile("cp.async.cg.shared.global [%0], [%1], 16, %2;\n"
                 :: "r"(s), "l"(src), "r"(sz));
}
__device__ __forceinline__ void cp_commit() {
    asm volatile("cp.async.commit_group;\n" ::: "memory");
}
template<int N>
__device__ __forceinline__ void cp_wait() {
    asm volatile("cp.async.wait_group %0;\n" :: "n"(N) : "memory");
}

// ---------------- fp16 prep (pool zero; deg zero on side stream) ------------
__global__ void init_prep_kernel(const float* __restrict__ x,
                                 const float* __restrict__ W1,
                                 const float* __restrict__ W2,
                                 __half* __restrict__ xh,
                                 __half* __restrict__ w1t,
                                 __half* __restrict__ w2t,
                                 float* __restrict__ pool) {
    size_t i = (size_t)blockIdx.x * blockDim.x + threadIdx.x;
    if (i < (size_t)NN * IND) xh[i] = __float2half_rn(x[i]);
    if (i < (size_t)F1 * IND) {
        int n = (int)(i / IND), k = (int)(i % IND);
        w1t[i] = __float2half_rn(W1[(size_t)k * F1 + n]);
    }
    if (i < (size_t)HIDC * F1) {
        int n = (int)(i / F1), k = (int)(i % F1);
        w2t[i] = __float2half_rn(W2[(size_t)k * HIDC + n]);
    }
    if (i < NG * HIDC) pool[i] = 0.f;
}

__global__ void zero_deg_kernel(int* __restrict__ deg) {
    int i = blockIdx.x * blockDim.x + threadIdx.x;
    if (i < NN) deg[i] = 0;
}

// ---------------- CSR construction ------------------------------------------
__global__ void deg_count_kernel(const int* __restrict__ ei, int* __restrict__ deg) {
    int e = blockIdx.x * blockDim.x + threadIdx.x;
    if (e >= ETOT) return;
    int d = (e < EE) ? ei[EE + e] : (e - EE);
    atomicAdd(&deg[d], 1);
}

__global__ void scan_a_kernel(const int* __restrict__ deg, int* __restrict__ part) {
    __shared__ int red[256];
    int i = blockIdx.x * 256 + threadIdx.x;
    int v = (i < NN) ? deg[i] : 0;
    red[threadIdx.x] = v;
    __syncthreads();
#pragma unroll
    for (int off = 128; off; off >>= 1) {
        if (threadIdx.x < off) red[threadIdx.x] += red[threadIdx.x + off];
        __syncthreads();
    }
    if (threadIdx.x == 0) part[blockIdx.x] = red[0];
}

__global__ void scan_c_kernel(const int* __restrict__ deg, const int* __restrict__ part,
                              int* __restrict__ rowptr, int* __restrict__ cursor) {
    __shared__ int sh[256];
    __shared__ int red[256];
    int t = threadIdx.x;
    int bid = blockIdx.x;
    int pv = (t < bid) ? part[t] : 0;     // SCAN_NB=196 <= 256
    red[t] = pv;
    __syncthreads();
#pragma unroll
    for (int off = 128; off; off >>= 1) {
        if (t < off) red[t] += red[t + off];
        __syncthreads();
    }
    int base = red[0];

    int i = bid * 256 + t;
    int v = (i < NN) ? deg[i] : 0;
    sh[t] = v;
    __syncthreads();
#pragma unroll
    for (int off = 1; off < 256; off <<= 1) {
        int u = (t >= off) ? sh[t - off] : 0;
        __syncthreads();
        sh[t] += u;
        __syncthreads();
    }
    if (i < NN) {
        int excl = base + sh[t] - v;
        rowptr[i] = excl;
        cursor[i] = excl;
    }
    if (i == NN - 1) rowptr[NN] = ETOT;
}

__global__ void csr_fill_kernel(const int* __restrict__ ei, int* __restrict__ cursor,
                                int* __restrict__ csr_src) {
    int e = blockIdx.x * blockDim.x + threadIdx.x;
    if (e >= ETOT) return;
    int s, d;
    if (e < EE) { s = ei[e]; d = ei[EE + e]; } else { s = d = e - EE; }
    int pos = atomicAdd(&cursor[d], 1);
    csr_src[pos] = s;
}

// ---------------- fp16 tensor-core GEMM, cp.async(2-stage) + ldmatrix -------
template<int BM, int BN, int WM, int NH, int MINB>
__global__ void __launch_bounds__((BM / WM) * (BN / 64) * 32, MINB)
mma_gemm_fused_kernel(const __half* __restrict__ A,
                      const __half* __restrict__ Bt,
                      __half* __restrict__ Ch,
                      const float* __restrict__ att_s,
                      const float* __restrict__ att_d,
                      float* __restrict__ AS,
                      float* __restrict__ AD,
                      int M, int N, int K) {
    constexpr int BK = 64;
    constexpr int WN = 64;
    constexpr int WARPS_M = BM / WM;
    constexpr int WARPS_N = BN / 64;
    constexpr int THREADS = WARPS_M * WARPS_N * 32;
    constexpr int MI = WM / 16;
    constexpr int NI = WN / 8;
    constexpr int NJ = NI / 2;
    constexpr int LDA = BK + 8;
    constexpr int LDB = BK + 8;
    constexpr int A_IT = (BM * (BK / 8)) / THREADS;
    constexpr int B_IT = (BN * (BK / 8)) / THREADS;

    extern __shared__ char smem_raw[];
    __half* Asm = (__half*)smem_raw;                                    // [2][BM][LDA]
    __half* Bsm = (__half*)(smem_raw + 2 * BM * LDA * sizeof(__half));

    int tid  = threadIdx.x;
    int wid  = tid >> 5;
    int lane = tid & 31;
    int wm = wid % WARPS_M;
    int wn = wid / WARPS_M;
    int gid = lane >> 2;
    int tg  = lane & 3;

    int blockRow = blockIdx.y * BM;
    int blockCol = blockIdx.x * BN;

    float acc[MI][NI][4];
#pragma unroll
    for (int i = 0; i < MI; i++)
#pragma unroll
        for (int j = 0; j < NI; j++)
#pragma unroll
            for (int v = 0; v < 4; v++) acc[i][j][v] = 0.f;

    const int KT = K / BK;

    auto load_tiles = [&](int kt, int stage) {
        int k0 = kt * BK;
        __half* Ad = Asm + (size_t)stage * BM * LDA;
        __half* Bd = Bsm + (size_t)stage * BN * LDB;
#pragma unroll
        for (int v = 0; v < A_IT; v++) {
            int idx = tid + v * THREADS;
            int r = idx >> 3, c = idx & 7;
            int gr = blockRow + r;
            cp_async16h(Ad + r * LDA + c * 8,
                        A + (size_t)gr * K + k0 + c * 8, gr < M);
        }
#pragma unroll
        for (int v = 0; v < B_IT; v++) {
            int idx = tid + v * THREADS;
            int r = idx >> 3, c = idx & 7;
            cp_async16h(Bd + r * LDB + c * 8,
                        Bt + (size_t)(blockCol + r) * K + k0 + c * 8, true);
        }
    };

    load_tiles(0, 0);
    cp_commit();

    int a_row = wm * WM + (lane & 15);
    int a_col = (lane >> 4) * 8;
    int b_row = wn * WN + (lane & 7) + (lane >> 4) * 8;
    int b_col = ((lane >> 3) & 1) * 8;

    int buf = 0;
    for (int kt = 0; kt < KT; kt++) {
        if (kt + 1 < KT) {
            load_tiles(kt + 1, buf ^ 1);
            cp_commit();
            cp_wait<1>();
        } else {
            cp_wait<0>();
        }
        __syncthreads();

        const __half* Asb = Asm + (size_t)buf * BM * LDA;
        const __half* Bsb = Bsm + (size_t)buf * BN * LDB;
        uint32_t a_addr[MI], b_addr[NJ];
#pragma unroll
        for (int mi = 0; mi < MI; mi++)
            a_addr[mi] = smem_u32(Asb + (size_t)(a_row + mi * 16) * LDA + a_col);
#pragma unroll
        for (int nj = 0; nj < NJ; nj++)
            b_addr[nj] = smem_u32(Bsb + (size_t)(b_row + nj * 16) * LDB + b_col);

#pragma unroll
        for (int kk = 0; kk < BK; kk += 16) {
            unsigned a[MI][4], b[NI][2];
#pragma unroll
            for (int mi = 0; mi < MI; mi++)
                ldsm_x4(a[mi][0], a[mi][1], a[mi][2], a[mi][3], a_addr[mi] + kk * 2);
#pragma unroll
            for (int nj = 0; nj < NJ; nj++)
                ldsm_x4(b[2 * nj][0], b[2 * nj][1], b[2 * nj + 1][0], b[2 * nj + 1][1],
                        b_addr[nj] + kk * 2);
#pragma unroll
            for (int mi = 0; mi < MI; mi++)
#pragma unroll
                for (int ni = 0; ni < NI; ni++)
                    mma_f16(acc[mi][ni], a[mi], b[ni]);
        }
        __syncthreads();
        buf ^= 1;
    }

    // ---- epilogue: fp16 write + fused per-head attention dots ----
    int head = (blockCol >> 6) + wn;
    float asv[NI][2], adv[NI][2];
#pragma unroll
    for (int ni = 0; ni < NI; ni++) {
        int c = head * 64 + ni * 8 + tg * 2;
        asv[ni][0] = att_s[c];     asv[ni][1] = att_s[c + 1];
        adv[ni][0] = att_d[c];     adv[ni][1] = att_d[c + 1];
    }

#pragma unroll
    for (int mi = 0; mi < MI; mi++) {
#pragma unroll
        for (int rh = 0; rh < 2; rh++) {
            int row = blockRow + wm * WM + mi * 16 + gid + rh * 8;
            float ps = 0.f, pd = 0.f;
#pragma unroll
            for (int ni = 0; ni < NI; ni++) {
                float c0 = acc[mi][ni][rh * 2];
                float c1 = acc[mi][ni][rh * 2 + 1];
                ps = fmaf(c0, asv[ni][0], fmaf(c1, asv[ni][1], ps));
                pd = fmaf(c0, adv[ni][0], fmaf(c1, adv[ni][1], pd));
            }
            ps += __shfl_xor_sync(0xffffffffu, ps, 1);
            ps += __shfl_xor_sync(0xffffffffu, ps, 2);
            pd += __shfl_xor_sync(0xffffffffu, pd, 1);
            pd += __shfl_xor_sync(0xffffffffu, pd, 2);
            if (tg == 0 && row < M) {
                AS[row * NH + head] = ps;
                AD[row * NH + head] = pd;
            }
            if (row < M) {
                int col = blockCol + wn * WN;
#pragma unroll
                for (int ni = 0; ni < NI; ni++) {
                    *(__half2*)(Ch + (size_t)row * N + col + ni * 8 + tg * 2) =
                        __floats2half2_rn(acc[mi][ni][rh * 2], acc[mi][ni][rh * 2 + 1]);
                }
            }
        }
    }
}

// ---------------- layer1 fused softmax+gather --------------------------------
// 64 threads per dst row; thread owns 8 channels (one 16B uint4 load/edge).
// Edge chunk = 8 (staging: 8 edges x 8 heads = 64 threads).
__global__ void gather1_kernel(const int* __restrict__ rowptr,
                               const int* __restrict__ csr_src,
                               const float* __restrict__ AS,
                               const float* __restrict__ AD,
                               const uint4* __restrict__ h1h,
                               const float* __restrict__ b1,
                               __half* __restrict__ out) {
    __shared__ int   ssrc[8];
    __shared__ float sex[8][NH1];
    __shared__ float sad[NH1];

    int row = blockIdx.x;
    int tid = threadIdx.x;          // 0..63
    int head = tid >> 3;            // channels 8*tid.., head = 8*tid/64
    int start = rowptr[row], end = rowptr[row + 1];

    if (tid < NH1) sad[tid] = AD[row * NH1 + tid];
    __syncthreads();

    float a0 = 0.f, a1 = 0.f, a2 = 0.f, a3 = 0.f;
    float a4 = 0.f, a5 = 0.f, a6 = 0.f, a7 = 0.f;
    float den = 0.f;

    for (int j0 = start; j0 < end; j0 += 8) {
        int m = end - j0; if (m > 8) m = 8;
        if (tid < m * NH1) {
            int e = tid >> 3, hh = tid & 7;
            int s = csr_src[j0 + e];
            if (hh == 0) ssrc[e] = s;
            float lg = AS[s * NH1 + hh] + sad[hh];
            lg = (lg > 0.f) ? lg : 0.2f * lg;
            sex[e][hh] = __expf(lg);
        }
        __syncthreads();
#pragma unroll 4
        for (int e = 0; e < m; e++) {
            int s = ssrc[e];
            float a = sex[e][head];
            uint4 u = h1h[(size_t)s * (F1 / 8) + tid];
            float2 f0 = __half22float2(*(__half2*)&u.x);
            float2 f1 = __half22float2(*(__half2*)&u.y);
            float2 f2 = __half22float2(*(__half2*)&u.z);
            float2 f3 = __half22float2(*(__half2*)&u.w);
            a0 = fmaf(f0.x, a, a0); a1 = fmaf(f0.y, a, a1);
            a2 = fmaf(f1.x, a, a2); a3 = fmaf(f1.y, a, a3);
            a4 = fmaf(f2.x, a, a4); a5 = fmaf(f2.y, a, a5);
            a6 = fmaf(f3.x, a, a6); a7 = fmaf(f3.y, a, a7);
            den += a;
        }
        __syncthreads();
    }
    float invd = 1.f / (den + 1e-16f);
    int ch = tid * 8;
    float4 bA = *(const float4*)(b1 + ch);
    float4 bB = *(const float4*)(b1 + ch + 4);
    float v0 = a0 * invd + bA.x;
    float v1 = a1 * invd + bA.y;
    float v2 = a2 * invd + bA.z;
    float v3 = a3 * invd + bA.w;
    float v4 = a4 * invd + bB.x;
    float v5 = a5 * invd + bB.y;
    float v6 = a6 * invd + bB.z;
    float v7 = a7 * invd + bB.w;
    v0 = (v0 > 0.f) ? v0 : (__expf(v0) - 1.f);
    v1 = (v1 > 0.f) ? v1 : (__expf(v1) - 1.f);
    v2 = (v2 > 0.f) ? v2 : (__expf(v2) - 1.f);
    v3 = (v3 > 0.f) ? v3 : (__expf(v3) - 1.f);
    v4 = (v4 > 0.f) ? v4 : (__expf(v4) - 1.f);
    v5 = (v5 > 0.f) ? v5 : (__expf(v5) - 1.f);
    v6 = (v6 > 0.f) ? v6 : (__expf(v6) - 1.f);
    v7 = (v7 > 0.f) ? v7 : (__expf(v7) - 1.f);
    uint4 o;
    *(__half2*)&o.x = __floats2half2_rn(v0, v1);
    *(__half2*)&o.y = __floats2half2_rn(v2, v3);
    *(__half2*)&o.z = __floats2half2_rn(v4, v5);
    *(__half2*)&o.w = __floats2half2_rn(v6, v7);
    *(uint4*)(out + (size_t)row * F1 + ch) = o;
}

// ---------------- layer2 fused softmax+gather --------------------------------
__global__ void gather2_kernel(const int* __restrict__ rowptr,
                               const int* __restrict__ csr_src,
                               const float* __restrict__ AS,
                               const float* __restrict__ AD,
                               const __half2* __restrict__ h2h,
                               const float* __restrict__ b2,
                               const int* __restrict__ batch,
                               float* __restrict__ pool) {
    int w = (blockIdx.x * blockDim.x + threadIdx.x) >> 5;
    int lane = threadIdx.x & 31;
    if (w >= NN) return;
    int start = rowptr[w], end = rowptr[w + 1];
    float ad_r = AD[w];
    int ch = lane * 2;
    float accx = 0.f, accy = 0.f, den = 0.f;

    for (int j0 = start; j0 < end; j0 += 32) {
        int m = end - j0; if (m > 32) m = 32;
        int s = 0; float ex = 0.f;
        if (lane < m) {
            s = csr_src[j0 + lane];
            float lg = AS[s] + ad_r;
            lg = (lg > 0.f) ? lg : 0.2f * lg;
            ex = __expf(lg);
        }
#pragma unroll 4
        for (int e = 0; e < m; e++) {
            float a  = __shfl_sync(0xffffffffu, ex, e);
            int   se = __shfl_sync(0xffffffffu, s,  e);
            float2 v = __half22float2(h2h[(size_t)se * 32 + lane]);
            accx = fmaf(v.x, a, accx);
            accy = fmaf(v.y, a, accy);
            den += a;
        }
    }
    float invd = 1.f / (den + 1e-16f);
    float vx = accx * invd + b2[ch];
    float vy = accy * invd + b2[ch + 1];
    vx = (vx > 0.f) ? vx : (__expf(vx) - 1.f);
    vy = (vy > 0.f) ? vy : (__expf(vy) - 1.f);
    int g = batch[w];
    atomicAdd(&pool[g * HIDC + ch],     vx);
    atomicAdd(&pool[g * HIDC + ch + 1], vy);
}

// ---------------- final FC (with inline graph-count binary search) ----------
__global__ void final_fc_kernel(const float* __restrict__ pool,
                                const int* __restrict__ batch,
                                const float* __restrict__ fcw,
                                const float* __restrict__ fcb,
                                float* __restrict__ out) {
    int t = threadIdx.x;
    if (t >= NG * ODIM) return;
    int g = t >> 1, o = t & 1;
    int lo = 0, hi = NN;
    while (lo < hi) { int mid = (lo + hi) >> 1; if (batch[mid] < g) lo = mid + 1; else hi = mid; }
    int a = lo, b = NN;
    while (a < b) { int mid = (a + b) >> 1; if (batch[mid] < g + 1) a = mid + 1; else b = mid; }
    float cc = (float)(a - lo);
    cc = (cc > 1.f) ? cc : 1.f;

    float s = 0.f;
#pragma unroll
    for (int c = 0; c < HIDC; c++) s += pool[g * HIDC + c] * fcw[c * ODIM + o];
    out[g * ODIM + o] = s / cc + fcb[o];
}

// ---------------- launcher ----------------------------------------------------
static inline int nblk(size_t n, int t) { return (int)((n + t - 1) / t); }

extern "C" void kernel_launch(void* const* d_in, const int* in_sizes, int n_in,
                              void* d_out, int out_size) {
    const float* x      = (const float*)d_in[0];
    const float* W1     = (const float*)d_in[1];
    const float* att_s1 = (const float*)d_in[2];
    const float* att_d1 = (const float*)d_in[3];
    const float* b1     = (const float*)d_in[4];
    const float* W2     = (const float*)d_in[5];
    const float* att_s2 = (const float*)d_in[6];
    const float* att_d2 = (const float*)d_in[7];
    const float* b2     = (const float*)d_in[8];
    const float* fcw    = (const float*)d_in[9];
    const float* fcb    = (const float*)d_in[10];
    const int*   ei     = (const int*)d_in[11];
    const int*   batch  = (const int*)d_in[12];
    float* out = (float*)d_out;

    float *AS1, *AD1, *AS2, *AD2, *POOL;
    __half *Xh, *W1T, *W2T, *H1h, *H1E, *H2h;
    int *DEG, *ROWPTR, *CURSOR, *CSRC, *PART;
    cudaGetSymbolAddress((void**)&Xh,    g_Xh);
    cudaGetSymbolAddress((void**)&W1T,   g_W1T);
    cudaGetSymbolAddress((void**)&W2T,   g_W2T);
    cudaGetSymbolAddress((void**)&H1h,   g_H1h);
    cudaGetSymbolAddress((void**)&H1E,   g_H1E);
    cudaGetSymbolAddress((void**)&H2h,   g_H2h);
    cudaGetSymbolAddress((void**)&AS1,   g_AS1);
    cudaGetSymbolAddress((void**)&AD1,   g_AD1);
    cudaGetSymbolAddress((void**)&AS2,   g_AS2);
    cudaGetSymbolAddress((void**)&AD2,   g_AD2);
    cudaGetSymbolAddress((void**)&POOL,  g_POOL);
    cudaGetSymbolAddress((void**)&DEG,    g_deg);
    cudaGetSymbolAddress((void**)&ROWPTR, g_rowptr);
    cudaGetSymbolAddress((void**)&CURSOR, g_cursor);
    cudaGetSymbolAddress((void**)&CSRC,   g_csr_src);
    cudaGetSymbolAddress((void**)&PART,   g_part);

    constexpr int SM1 = 2 * (128 * 72 + 128 * 72) * 2;  // 73728
    constexpr int SM2 = 2 * (64 * 72 + 64 * 72) * 2;    // 36864
    cudaFuncSetAttribute((const void*)mma_gemm_fused_kernel<128, 128, 32, NH1, 2>,
                         cudaFuncAttributeMaxDynamicSharedMemorySize, SM1);
    cudaFuncSetAttribute((const void*)mma_gemm_fused_kernel<64, 64, 16, 1, 6>,
                         cudaFuncAttributeMaxDynamicSharedMemorySize, SM2);

    // side stream + fork/join events (created once; identical work every call)
    static cudaStream_t sB = nullptr;
    static cudaEvent_t  eFork = nullptr, eJoin = nullptr;
    if (sB == nullptr) {
        cudaStreamCreateWithFlags(&sB, cudaStreamNonBlocking);
        cudaEventCreateWithFlags(&eFork, cudaEventDisableTiming);
        cudaEventCreateWithFlags(&eJoin, cudaEventDisableTiming);
    }

    // ---- fork: CSR chain on side stream, prep+GEMM1 on main stream ----
    cudaEventRecord(eFork, 0);
    cudaStreamWaitEvent(sB, eFork, 0);

    zero_deg_kernel<<<nblk(NN, 256), 256, 0, sB>>>(DEG);
    deg_count_kernel<<<nblk(ETOT, 256), 256, 0, sB>>>(ei, DEG);
    scan_a_kernel<<<SCAN_NB, 256, 0, sB>>>(DEG, PART);
    scan_c_kernel<<<SCAN_NB, 256, 0, sB>>>(DEG, PART, ROWPTR, CURSOR);
    csr_fill_kernel<<<nblk(ETOT, 256), 256, 0, sB>>>(ei, CURSOR, CSRC);
    cudaEventRecord(eJoin, sB);

    init_prep_kernel<<<nblk((size_t)NN * IND, 256), 256>>>(x, W1, W2, Xh, W1T, W2T, POOL);
    {
        dim3 grid(F1 / 128, (NN + 127) / 128);
        mma_gemm_fused_kernel<128, 128, 32, NH1, 2><<<grid, 256, SM1>>>(
            Xh, W1T, H1h, att_s1, att_d1, AS1, AD1, NN, F1, IND);
    }

    // ---- join ----
    cudaStreamWaitEvent(0, eJoin, 0);

    // layer1 gather (64 threads/row, uint4 loads)
    gather1_kernel<<<NN, 64>>>(ROWPTR, CSRC, AS1, AD1, (const uint4*)H1h, b1, H1E);

    // GEMM2
    {
        dim3 grid(1, (NN + 63) / 64);
        mma_gemm_fused_kernel<64, 64, 16, 1, 6><<<grid, 128, SM2>>>(
            H1E, W2T, H2h, att_s2, att_d2, AS2, AD2, NN, HIDC, F1);
    }

    // layer2 gather
    gather2_kernel<<<nblk((size_t)NN * 32, 256), 256>>>(
        ROWPTR, CSRC, AS2, AD2, (const __half2*)H2h, b2, batch, POOL);

    // final FC (+ inline counts)
    final_fc_kernel<<<1, 128>>>(POOL, batch, fcw, fcb, out);
}